// round 2
// baseline (speedup 1.0000x reference)
#include <cuda_runtime.h>
#include <math.h>

#define NN 10000
#define EE 160000
#define BB 64
#define DD 128
#define MM 32
#define EINN 321
#define H1 642
#define KK 5
#define FH 768
#define F2 256
#define FASTRIDE 644

typedef unsigned long long u64;

// ---------------- scratch (zero-initialized device globals) ----------------
__device__ float d_feats[NN*DD];
__device__ float d_ea[EE*65];
__device__ float d_deg[NN];
__device__ float d_FA[NN*FASTRIDE + 256];
__device__ float d_FB[NN*FASTRIDE + 256];
__device__ float d_msum[NN*MM];
__device__ float d_xcat[NN*160];
__device__ float d_fcat[NN*FH];
__device__ float d_f1[NN*F2];
__device__ float d_f2[NN*F2];
__device__ float d_gsum[BB*F2];
__device__ float d_gcnt[BB];

__device__ __forceinline__ float siluf(float x){ return x/(1.f+expf(-x)); }

// ---- packed f32x2 helpers ----
__device__ __forceinline__ u64 pk2(float lo, float hi){
  u64 r; asm("mov.b64 %0,{%1,%2};" : "=l"(r) : "f"(lo), "f"(hi)); return r;
}
__device__ __forceinline__ u64 dupf(float x){
  u64 r; asm("mov.b64 %0,{%1,%1};" : "=l"(r) : "f"(x)); return r;
}
__device__ __forceinline__ void fma2(u64 &d, u64 a, u64 b){
  asm("fma.rn.f32x2 %0,%1,%2,%0;" : "+l"(d) : "l"(a), "l"(b));
}
__device__ __forceinline__ float2 up2(u64 v){
  float2 r; asm("mov.b64 {%0,%1},%2;" : "=f"(r.x), "=f"(r.y) : "l"(v)); return r;
}

// ---------------- init / zero kernels ----------------
__global__ void k_zero_init(){
  int i = blockIdx.x*256+threadIdx.x;
  if(i<NN) d_deg[i]=0.f;
  if(i<BB*F2) d_gsum[i]=0.f;
  if(i<BB) d_gcnt[i]=0.f;
}
__global__ void k_zero_msum(){
  int i = blockIdx.x*256+threadIdx.x;
  d_msum[i]=0.f;
}
__global__ void k_feats(const float* __restrict__ emb, const int* __restrict__ atomids){
  int n=blockIdx.x; int c=threadIdx.x;
  float v=emb[atomids[n]*DD+c];
  d_feats[n*DD+c]=v;
  d_fcat[(size_t)n*FH+c]=v;
}
__global__ void k_deg(const int* __restrict__ eidx){
  int e=blockIdx.x*256+threadIdx.x;
  atomicAdd(&d_deg[eidx[EE+e]],1.f);
}
__global__ void k_ea(const float* __restrict__ coords, const int* __restrict__ eidx){
  int e=blockIdx.x*256+threadIdx.x;
  int s=eidx[e], t2=eidx[EE+e];
  float dx=coords[3*s]-coords[3*t2];
  float dy=coords[3*s+1]-coords[3*t2+1];
  float dz=coords[3*s+2]-coords[3*t2+2];
  float d=dx*dx+dy*dy+dz*dz;
  float* o=&d_ea[(size_t)e*65];
  float x=d;
  #pragma unroll
  for(int i=0;i<32;i++){
    float sv,cv; sincosf(x,&sv,&cv);
    o[i]=sv; o[32+i]=cv;
    x*=0.5f;
  }
  o[64]=d;
}

// ---------------- per-layer: FA/FB = feats @ W1[part] ----------------
__global__ void __launch_bounds__(256) k_fab(const float* __restrict__ keW1,int k){
  extern __shared__ float sm[];
  float* s_f = sm;               // 64*129
  float* s_w = sm + 64*129;      // 128*64
  int zc=blockIdx.z;
  const float* W = keW1 + (size_t)k*EINN*H1 + (size_t)(zc?DD:0)*H1;
  int jc0=blockIdx.x*64, n0=blockIdx.y*64;
  for(int i=threadIdx.x;i<64*DD;i+=256){int r=i>>7,c=i&127;int n=n0+r; s_f[r*129+c]= (n<NN)? d_feats[(size_t)n*DD+c]:0.f;}
  for(int i=threadIdx.x;i<DD*64;i+=256){int p=i>>6,c=i&63;int j=jc0+c; s_w[i]= (j<H1)? W[(size_t)p*H1+j]:0.f;}
  __syncthreads();
  int r0=(threadIdx.x>>4)*4, c0=(threadIdx.x&15)*4;
  u64 acc[4][2];
  #pragma unroll
  for(int i=0;i<4;i++){acc[i][0]=0ull;acc[i][1]=0ull;}
  #pragma unroll 4
  for(int p=0;p<DD;p++){
    ulonglong2 w=*(ulonglong2*)(s_w+p*64+c0);
    #pragma unroll
    for(int i=0;i<4;i++){ u64 a=dupf(s_f[(r0+i)*129+p]);
      fma2(acc[i][0],a,w.x); fma2(acc[i][1],a,w.y); }
  }
  float* OUT = zc? d_FB: d_FA;
  #pragma unroll
  for(int i=0;i<4;i++){int n=n0+r0+i; if(n<NN){
    float2 u0=up2(acc[i][0]), u1=up2(acc[i][1]);
    float v[4]={u0.x,u0.y,u1.x,u1.y};
    #pragma unroll
    for(int j=0;j<4;j++){int jj=jc0+c0+j; if(jj<FASTRIDE) OUT[(size_t)n*FASTRIDE+jj]=v[j];}
  }}
}

// ---------------- per-layer: fused edge MLP + LN + scatter ----------------
// grid 1250, 256 thr, dynamic smem; tiles: GEMM1 4r x 8c, GEMM2 4r x 4c
__global__ void __launch_bounds__(256,2) k_edge(const int* __restrict__ eidx,
   const float* __restrict__ keW1,const float* __restrict__ keb1,
   const float* __restrict__ keW2,const float* __restrict__ keb2,
   const float* __restrict__ keng,const float* __restrict__ kenb,int k){
  extern __shared__ float sm[];
  float* s_ea = sm;                    // 128*66 = 8448
  float* s_w1 = s_ea + 128*66;         // 65*64  = 4160
  float* s_h  = s_w1 + 65*64;          // 128*66 = 8448
  float* s_w2 = s_h + 128*66;          // 64*32  = 2048
  float* s_b1 = s_w2 + 64*32;          // 64
  float* s_b2 = s_b1 + 64;             // 32
  float* s_g  = s_b2 + 32;             // 32
  float* s_bt = s_g + 32;              // 32
  int* s_dst = (int*)(s_bt+32);        // 128
  int* s_src = s_dst + 128;            // 128
  int tid=threadIdx.x;
  int e0=blockIdx.x*128;
  for(int i=tid;i<128*65;i+=256){ int r=i/65, c=i-r*65; s_ea[r*66+c]=d_ea[(size_t)e0*65 + i]; }
  if(tid<128){ s_dst[tid]=eidx[EE+e0+tid]; s_src[tid]=eidx[e0+tid]; }
  if(tid>=128 && tid<160){ int c=tid-128; s_b2[c]=keb2[k*MM+c]; s_g[c]=keng[k*MM+c]; s_bt[c]=kenb[k*MM+c]; }
  const float* W1c = keW1 + (size_t)k*EINN*H1 + (size_t)256*H1;
  const float* W2  = keW2 + (size_t)k*H1*MM;
  const float* B1  = keb1 + (size_t)k*H1;
  int r0=(tid>>3)*4;          // 0..124
  int c0=(tid&7)*8;           // 0..56 (GEMM1 cols)
  int c2=(tid&7)*4;           // 0..28 (GEMM2 cols)
  u64 acc[4][2];
  #pragma unroll
  for(int i=0;i<4;i++){acc[i][0]=0ull;acc[i][1]=0ull;}
  for(int ch=0; ch<11; ch++){
    int jc0=ch*64;
    __syncthreads();
    for(int i=tid;i<65*64;i+=256){int p=i>>6,c=i&63;int j=jc0+c; s_w1[i]=(j<H1)?W1c[(size_t)p*H1+j]:0.f;}
    for(int i=tid;i<64*32;i+=256){int p=i>>5,c=i&31;int j=jc0+p; s_w2[i]=(j<H1)?W2[(size_t)j*MM+c]:0.f;}
    if(tid<64){int j=jc0+tid; s_b1[tid]=(j<H1)?B1[j]:0.f;}
    __syncthreads();
    u64 t2[4][4];
    #pragma unroll
    for(int i=0;i<4;i++){t2[i][0]=0ull;t2[i][1]=0ull;t2[i][2]=0ull;t2[i][3]=0ull;}
    #pragma unroll 5
    for(int p=0;p<65;p++){
      ulonglong2 wA=*(ulonglong2*)(s_w1+p*64+c0);
      ulonglong2 wB=*(ulonglong2*)(s_w1+p*64+c0+4);
      #pragma unroll
      for(int i=0;i<4;i++){ u64 a=dupf(s_ea[(r0+i)*66+p]);
        fma2(t2[i][0],a,wA.x); fma2(t2[i][1],a,wA.y);
        fma2(t2[i][2],a,wB.x); fma2(t2[i][3],a,wB.y); }
    }
    float4 bA=*(float4*)(s_b1+c0);
    float4 bB=*(float4*)(s_b1+c0+4);
    #pragma unroll
    for(int i=0;i<4;i++){
      int rr=r0+i;
      int nd=s_dst[rr], ns=s_src[rr];
      const float* fap=d_FA+(size_t)nd*FASTRIDE+jc0+c0;
      const float* fbp=d_FB+(size_t)ns*FASTRIDE+jc0+c0;
      float4 fa0=*(const float4*)(fap), fa1=*(const float4*)(fap+4);
      float4 fb0=*(const float4*)(fbp), fb1=*(const float4*)(fbp+4);
      float2 u0=up2(t2[i][0]), u1=up2(t2[i][1]), u2=up2(t2[i][2]), u3=up2(t2[i][3]);
      float h0=siluf(u0.x+bA.x+fa0.x+fb0.x);
      float h1=siluf(u0.y+bA.y+fa0.y+fb0.y);
      float h2=siluf(u1.x+bA.z+fa0.z+fb0.z);
      float h3=siluf(u1.y+bA.w+fa0.w+fb0.w);
      float h4=siluf(u2.x+bB.x+fa1.x+fb1.x);
      float h5=siluf(u2.y+bB.y+fa1.y+fb1.y);
      float h6=siluf(u3.x+bB.z+fa1.z+fb1.z);
      float h7=siluf(u3.y+bB.w+fa1.w+fb1.w);
      float* hp=s_h+rr*66+c0;
      *(float2*)(hp)  =make_float2(h0,h1);
      *(float2*)(hp+2)=make_float2(h2,h3);
      *(float2*)(hp+4)=make_float2(h4,h5);
      *(float2*)(hp+6)=make_float2(h6,h7);
    }
    __syncthreads();
    #pragma unroll 4
    for(int p=0;p<64;p++){
      ulonglong2 w=*(ulonglong2*)(s_w2+p*32+c2);
      #pragma unroll
      for(int i=0;i<4;i++){ u64 a=dupf(s_h[(r0+i)*66+p]);
        fma2(acc[i][0],a,w.x); fma2(acc[i][1],a,w.y); }
    }
  }
  #pragma unroll
  for(int i=0;i<4;i++){
    float2 q0=up2(acc[i][0]), q1=up2(acc[i][1]);
    float v0=siluf(q0.x+s_b2[c2+0]);
    float v1=siluf(q0.y+s_b2[c2+1]);
    float v2=siluf(q1.x+s_b2[c2+2]);
    float v3=siluf(q1.y+s_b2[c2+3]);
    float s=v0+v1+v2+v3, ss=v0*v0+v1*v1+v2*v2+v3*v3;
    #pragma unroll
    for(int o=1;o<8;o<<=1){ s+=__shfl_xor_sync(0xffffffffu,s,o); ss+=__shfl_xor_sync(0xffffffffu,ss,o); }
    float mu=s*(1.f/MM);
    float var=ss*(1.f/MM)-mu*mu;
    float inv=rsqrtf(var+1e-5f);
    float m0=(v0-mu)*inv*s_g[c2+0]+s_bt[c2+0];
    float m1=(v1-mu)*inv*s_g[c2+1]+s_bt[c2+1];
    float m2=(v2-mu)*inv*s_g[c2+2]+s_bt[c2+2];
    float m3=(v3-mu)*inv*s_g[c2+3]+s_bt[c2+3];
    float* dsta=&d_msum[(size_t)s_dst[r0+i]*MM+c2];
    atomicAdd(dsta+0,m0); atomicAdd(dsta+1,m1);
    atomicAdd(dsta+2,m2); atomicAdd(dsta+3,m3);
  }
}

// ---------------- per-layer: xcat = [LN(feats) | LN(msum/deg)] ----------------
__global__ void k_xcat(const float* __restrict__ keng,const float* __restrict__ kenb,
                       const float* __restrict__ kn1g,const float* __restrict__ kn1b,int k){
  int warp=threadIdx.x>>5, lane=threadIdx.x&31;
  int n=blockIdx.x*8+warp;
  const float* g1=kn1g+(size_t)k*128; const float* b1=kn1b+(size_t)k*128;
  float v[4],s=0.f,ss=0.f;
  #pragma unroll
  for(int i=0;i<4;i++){ float x=d_feats[(size_t)n*128+lane+32*i]; v[i]=x; s+=x; ss+=x*x; }
  #pragma unroll
  for(int o=16;o;o>>=1){ s+=__shfl_xor_sync(0xffffffffu,s,o); ss+=__shfl_xor_sync(0xffffffffu,ss,o); }
  float mu=s*(1.f/128), var=ss*(1.f/128)-mu*mu, inv=rsqrtf(var+1e-5f);
  #pragma unroll
  for(int i=0;i<4;i++){ int c=lane+32*i; d_xcat[(size_t)n*160+c]=(v[i]-mu)*inv*g1[c]+b1[c]; }
  float m=d_msum[(size_t)n*MM+lane]/fmaxf(d_deg[n],1.f);
  float s2=m, ss2=m*m;
  #pragma unroll
  for(int o=16;o;o>>=1){ s2+=__shfl_xor_sync(0xffffffffu,s2,o); ss2+=__shfl_xor_sync(0xffffffffu,ss2,o); }
  float mu2=s2*(1.f/MM), var2=ss2*(1.f/MM)-mu2*mu2, inv2=rsqrtf(var2+1e-5f);
  d_xcat[(size_t)n*160+128+lane]=(m-mu2)*inv2*keng[k*MM+lane]+kenb[k*MM+lane];
}

// ---------------- per-layer: fused node MLP + LN + residual ----------------
__global__ void __launch_bounds__(256) k_node(const float* __restrict__ knW1,const float* __restrict__ knb1,
    const float* __restrict__ knW2,const float* __restrict__ knb2,
    const float* __restrict__ kn2g,const float* __restrict__ kn2b,int k){
  extern __shared__ float sm[];
  float* s_x=sm;            // 64*161=10304
  float* s_h=s_x+10304;     // 64*257=16448
  float* s_w=s_h+16448;     // 256*64=16384
  int tid=threadIdx.x;
  int n0=blockIdx.x*64;
  const float* W1=knW1+(size_t)k*160*256;
  const float* B1=knb1+(size_t)k*256;
  const float* W2=knW2+(size_t)k*256*128;
  const float* B2=knb2+(size_t)k*128;
  const float* G =kn2g+(size_t)k*128;
  const float* BT=kn2b+(size_t)k*128;
  for(int i=tid;i<64*160;i+=256){int r=i/160,c=i-r*160;int n=n0+r; s_x[r*161+c]= (n<NN)? d_xcat[(size_t)n*160+c]:0.f;}
  int r0=(tid>>4)*4, c0=(tid&15)*4;
  for(int oc=0;oc<4;oc++){
    __syncthreads();
    for(int i=tid;i<160*64;i+=256){int p=i>>6,c=i&63; s_w[i]=W1[(size_t)p*256+oc*64+c];}
    __syncthreads();
    u64 t2[4][2];
    #pragma unroll
    for(int i=0;i<4;i++){t2[i][0]=0ull;t2[i][1]=0ull;}
    #pragma unroll 4
    for(int p=0;p<160;p++){
      ulonglong2 w=*(ulonglong2*)(s_w+p*64+c0);
      #pragma unroll
      for(int i=0;i<4;i++){ u64 a=dupf(s_x[(r0+i)*161+p]);
        fma2(t2[i][0],a,w.x); fma2(t2[i][1],a,w.y); }
    }
    #pragma unroll
    for(int i=0;i<4;i++){
      float2 u0=up2(t2[i][0]), u1=up2(t2[i][1]);
      float v[4]={u0.x,u0.y,u1.x,u1.y};
      #pragma unroll
      for(int j=0;j<4;j++){ int col=oc*64+c0+j;
        s_h[(r0+i)*257+col]=siluf(v[j]+__ldg(&B1[col])); }
    }
  }
  __syncthreads();
  for(int oc=0;oc<2;oc++){
    if(oc) __syncthreads();
    for(int i=tid;i<256*64;i+=256){int p=i>>6,c=i&63; s_w[i]=W2[(size_t)p*128+oc*64+c];}
    __syncthreads();
    u64 t2[4][2];
    #pragma unroll
    for(int i=0;i<4;i++){t2[i][0]=0ull;t2[i][1]=0ull;}
    #pragma unroll 4
    for(int p=0;p<256;p++){
      ulonglong2 w=*(ulonglong2*)(s_w+p*64+c0);
      #pragma unroll
      for(int i=0;i<4;i++){ u64 a=dupf(s_h[(r0+i)*257+p]);
        fma2(t2[i][0],a,w.x); fma2(t2[i][1],a,w.y); }
    }
    #pragma unroll
    for(int i=0;i<4;i++){
      float2 u0=up2(t2[i][0]), u1=up2(t2[i][1]);
      float v[4]={u0.x,u0.y,u1.x,u1.y};
      #pragma unroll
      for(int j=0;j<4;j++){ int col=oc*64+c0+j;
        s_x[(r0+i)*129+col]=v[j]+__ldg(&B2[col]); }
    }
  }
  __syncthreads();
  int w=tid>>5, lane=tid&31;
  for(int rr=w; rr<64; rr+=8){
    int n=n0+rr;
    float v[4],s=0.f,ss=0.f;
    #pragma unroll
    for(int i=0;i<4;i++){ float x=s_x[rr*129+lane+32*i]; v[i]=x; s+=x; ss+=x*x; }
    #pragma unroll
    for(int o=16;o;o>>=1){ s+=__shfl_xor_sync(0xffffffffu,s,o); ss+=__shfl_xor_sync(0xffffffffu,ss,o); }
    float mu=s*(1.f/128), var=ss*(1.f/128)-mu*mu, inv=rsqrtf(var+1e-5f);
    if(n<NN){
      #pragma unroll
      for(int i=0;i<4;i++){ int c=lane+32*i;
        float nv=(v[i]-mu)*inv*G[c]+BT[c];
        float f=d_feats[(size_t)n*128+c]+nv;
        d_feats[(size_t)n*128+c]=f;
        d_fcat[(size_t)n*FH+(size_t)(k+1)*128+c]=f; }
    }
  }
}

// ---------------- head MLP ----------------
__global__ void __launch_bounds__(256) k_fnn0(const float* __restrict__ W,const float* __restrict__ b){
  __shared__ float s_a[64*65];
  __shared__ float s_w[64*64];
  int tid=threadIdx.x;
  int jc0=blockIdx.x*64, n0=blockIdx.y*64;
  int r0=(tid>>4)*4, c0=(tid&15)*4;
  u64 acc[4][2];
  #pragma unroll
  for(int i=0;i<4;i++){acc[i][0]=0ull;acc[i][1]=0ull;}
  for(int ch=0;ch<12;ch++){
    __syncthreads();
    for(int i=tid;i<64*64;i+=256){int r=i>>6,c=i&63;int n=n0+r; s_a[r*65+c]= (n<NN)? siluf(d_fcat[(size_t)n*FH+ch*64+c]) : 0.f;}
    for(int i=tid;i<64*64;i+=256){int p=i>>6,c=i&63; s_w[i]=W[(size_t)(ch*64+p)*F2 + jc0+c];}
    __syncthreads();
    #pragma unroll 4
    for(int p=0;p<64;p++){
      ulonglong2 w=*(ulonglong2*)(s_w+p*64+c0);
      #pragma unroll
      for(int i=0;i<4;i++){ u64 a=dupf(s_a[(r0+i)*65+p]);
        fma2(acc[i][0],a,w.x); fma2(acc[i][1],a,w.y); }
    }
  }
  #pragma unroll
  for(int i=0;i<4;i++){int n=n0+r0+i; if(n<NN){
    float2 u0=up2(acc[i][0]), u1=up2(acc[i][1]);
    float v[4]={u0.x,u0.y,u1.x,u1.y};
    #pragma unroll
    for(int j=0;j<4;j++) d_f1[(size_t)n*F2+jc0+c0+j]=siluf(v[j]+__ldg(&b[jc0+c0+j]));
  }}
}

__global__ void __launch_bounds__(256) k_fnn(const float* __restrict__ W,const float* __restrict__ b,int which){
  __shared__ float s_a[64*65];
  __shared__ float s_w[64*64];
  const float* fin = which? d_f2 : d_f1;
  float* fout = which? d_f1 : d_f2;
  int tid=threadIdx.x;
  int jc0=blockIdx.x*64, n0=blockIdx.y*64;
  int r0=(tid>>4)*4, c0=(tid&15)*4;
  u64 acc[4][2];
  #pragma unroll
  for(int i=0;i<4;i++){acc[i][0]=0ull;acc[i][1]=0ull;}
  for(int ch=0;ch<4;ch++){
    __syncthreads();
    for(int i=tid;i<64*64;i+=256){int r=i>>6,c=i&63;int n=n0+r; s_a[r*65+c]= (n<NN)? fin[(size_t)n*F2+ch*64+c] : 0.f;}
    for(int i=tid;i<64*64;i+=256){int p=i>>6,c=i&63; s_w[i]=W[(size_t)(ch*64+p)*F2 + jc0+c];}
    __syncthreads();
    #pragma unroll 4
    for(int p=0;p<64;p++){
      ulonglong2 w=*(ulonglong2*)(s_w+p*64+c0);
      #pragma unroll
      for(int i=0;i<4;i++){ u64 a=dupf(s_a[(r0+i)*65+p]);
        fma2(acc[i][0],a,w.x); fma2(acc[i][1],a,w.y); }
    }
  }
  #pragma unroll
  for(int i=0;i<4;i++){int n=n0+r0+i; if(n<NN){
    float2 u0=up2(acc[i][0]), u1=up2(acc[i][1]);
    float v[4]={u0.x,u0.y,u1.x,u1.y};
    #pragma unroll
    for(int j=0;j<4;j++) fout[(size_t)n*F2+jc0+c0+j]=siluf(v[j]+__ldg(&b[jc0+c0+j]));
  }}
}

__global__ void k_pool(const int* __restrict__ batch){
  int n=blockIdx.x; int c=threadIdx.x;
  int b=batch[n];
  atomicAdd(&d_gsum[b*F2+c], d_f1[(size_t)n*F2+c]);
  if(c==0) atomicAdd(&d_gcnt[b],1.f);
}

__global__ void k_final(const float* __restrict__ gW0,const float* __restrict__ gb0,
                        const float* __restrict__ gW1,const float* __restrict__ gb1,
                        const float* __restrict__ gW2,const float* __restrict__ gb2,
                        float* __restrict__ out){
  __shared__ float s_g[256], s_h[256], s_red[8];
  int b=blockIdx.x, t=threadIdx.x;
  float cnt=fmaxf(d_gcnt[b],1.f);
  s_g[t]=d_gsum[b*F2+t]/cnt;
  __syncthreads();
  float a=gb0[t];
  #pragma unroll 8
  for(int p=0;p<256;p++) a+=s_g[p]*gW0[p*256+t];
  s_h[t]=siluf(a);
  __syncthreads();
  a=gb1[t];
  #pragma unroll 8
  for(int p=0;p<256;p++) a+=s_h[p]*gW1[p*256+t];
  float h=siluf(a);
  float v=h*gW2[t];
  #pragma unroll
  for(int o=16;o;o>>=1) v+=__shfl_xor_sync(0xffffffffu,v,o);
  if((t&31)==0) s_red[t>>5]=v;
  __syncthreads();
  if(t==0){ float tot=0.f;
    #pragma unroll
    for(int i=0;i<8;i++) tot+=s_red[i];
    out[b]=tot+gb2[0]; }
}

// ---------------- host ----------------
extern "C" void kernel_launch(void* const* d_in, const int* in_sizes, int n_in,
                              void* d_out, int out_size){
  const float* coords =(const float*)d_in[0];
  const int*   atomids=(const int*)d_in[1];
  const int*   eidx   =(const int*)d_in[2];
  const int*   batch  =(const int*)d_in[3];
  int s = (in_sizes[4]==11*DD) ? 4 : 5;   // skip num_graphs scalar if present
  const float* emb =(const float*)d_in[s+0];
  const float* keW1=(const float*)d_in[s+1];
  const float* keb1=(const float*)d_in[s+2];
  const float* keW2=(const float*)d_in[s+3];
  const float* keb2=(const float*)d_in[s+4];
  const float* keng=(const float*)d_in[s+5];
  const float* kenb=(const float*)d_in[s+6];
  const float* kn1g=(const float*)d_in[s+7];
  const float* kn1b=(const float*)d_in[s+8];
  const float* knW1=(const float*)d_in[s+9];
  const float* knb1=(const float*)d_in[s+10];
  const float* knW2=(const float*)d_in[s+11];
  const float* knb2=(const float*)d_in[s+12];
  const float* kn2g=(const float*)d_in[s+13];
  const float* kn2b=(const float*)d_in[s+14];
  const float* fW0 =(const float*)d_in[s+15];
  const float* fb0 =(const float*)d_in[s+16];
  const float* fW1 =(const float*)d_in[s+17];
  const float* fb1 =(const float*)d_in[s+18];
  const float* fW2 =(const float*)d_in[s+19];
  const float* fb2 =(const float*)d_in[s+20];
  const float* gW0 =(const float*)d_in[s+21];
  const float* gb0 =(const float*)d_in[s+22];
  const float* gW1 =(const float*)d_in[s+23];
  const float* gb1 =(const float*)d_in[s+24];
  const float* gW2 =(const float*)d_in[s+25];
  const float* gb2 =(const float*)d_in[s+26];
  float* out=(float*)d_out;

  const int FAB_SM  = (64*129 + 128*64)*4;                 // 65792
  const int EDGE_SM = (128*66 + 65*64 + 128*66 + 64*32 + 64+32+32+32)*4 + 256*4; // 94080
  const int NODE_SM = (10304+16448+16384)*4;               // 172544
  cudaFuncSetAttribute(k_fab,  cudaFuncAttributeMaxDynamicSharedMemorySize, FAB_SM);
  cudaFuncSetAttribute(k_edge, cudaFuncAttributeMaxDynamicSharedMemorySize, EDGE_SM);
  cudaFuncSetAttribute(k_node, cudaFuncAttributeMaxDynamicSharedMemorySize, NODE_SM);

  k_zero_init<<<65,256>>>();
  k_feats<<<NN,128>>>(emb,atomids);
  k_deg<<<EE/256,256>>>(eidx);
  k_ea<<<EE/256,256>>>(coords,eidx);
  for(int k=0;k<KK;k++){
    k_zero_msum<<<(NN*MM)/256,256>>>();
    k_fab<<<dim3(11,157,2),256,FAB_SM>>>(keW1,k);
    k_edge<<<EE/128,256,EDGE_SM>>>(eidx,keW1,keb1,keW2,keb2,keng,kenb,k);
    k_xcat<<<NN/8,256>>>(keng,kenb,kn1g,kn1b,k);
    k_node<<<157,256,NODE_SM>>>(knW1,knb1,knW2,knb2,kn2g,kn2b,k);
  }
  k_fnn0<<<dim3(4,157),256>>>(fW0,fb0);
  k_fnn<<<dim3(4,157),256>>>(fW1,fb1,0);
  k_fnn<<<dim3(4,157),256>>>(fW2,fb2,1);
  k_pool<<<NN,256>>>(batch);
  k_final<<<BB,256>>>(gW0,gb0,gW1,gb1,gW2,gb2,out);
}

// round 3
// speedup vs baseline: 1.3406x; 1.3406x over previous
#include <cuda_runtime.h>
#include <math.h>

#define NN 10000
#define EE 160000
#define BB 64
#define DD 128
#define MM 32
#define EINN 321
#define H1 642
#define KK 5
#define FH 768
#define F2 256
#define FASTRIDE 644

// ---------------- scratch (zero-initialized device globals) ----------------
__device__ float d_feats[NN*DD];
__device__ float d_ea[EE*65];
__device__ float d_deg[NN];
__device__ float d_FA[NN*FASTRIDE + 256];
__device__ float d_FB[NN*FASTRIDE + 256];
__device__ float d_msum[NN*MM];
__device__ float d_xcat[NN*160];
__device__ float d_fcat[NN*FH];
__device__ float d_f1[NN*F2];
__device__ float d_f2[NN*F2];
__device__ float d_gsum[BB*F2];
__device__ float d_gcnt[BB];

__device__ __forceinline__ float siluf(float x){ return x/(1.f+expf(-x)); }

__device__ __forceinline__ float tf32r(float x){
  float r; asm("cvt.rna.tf32.f32 %0,%1;" : "=f"(r) : "f"(x)); return r;
}
__device__ __forceinline__ void mma8(float4 &c, unsigned a0,unsigned a1,unsigned a2,unsigned a3,
                                     unsigned b0,unsigned b1){
  asm("mma.sync.aligned.m16n8k8.row.col.f32.tf32.tf32.f32 "
      "{%0,%1,%2,%3},{%4,%5,%6,%7},{%8,%9},{%0,%1,%2,%3};"
      : "+f"(c.x),"+f"(c.y),"+f"(c.z),"+f"(c.w)
      : "r"(a0),"r"(a1),"r"(a2),"r"(a3),"r"(b0),"r"(b1));
}

// ---------------- init / zero kernels ----------------
__global__ void k_zero_init(){
  int i = blockIdx.x*256+threadIdx.x;
  if(i<NN) d_deg[i]=0.f;
  if(i<BB*F2) d_gsum[i]=0.f;
  if(i<BB) d_gcnt[i]=0.f;
}
__global__ void k_zero_msum(){
  int i = blockIdx.x*256+threadIdx.x;
  d_msum[i]=0.f;
}
__global__ void k_feats(const float* __restrict__ emb, const int* __restrict__ atomids){
  int n=blockIdx.x; int c=threadIdx.x;
  float v=emb[atomids[n]*DD+c];
  d_feats[n*DD+c]=v;
  d_fcat[(size_t)n*FH+c]=v;
}
__global__ void k_deg(const int* __restrict__ eidx){
  int e=blockIdx.x*256+threadIdx.x;
  atomicAdd(&d_deg[eidx[EE+e]],1.f);
}
__global__ void k_ea(const float* __restrict__ coords, const int* __restrict__ eidx){
  int e=blockIdx.x*256+threadIdx.x;
  int s=eidx[e], t2=eidx[EE+e];
  float dx=coords[3*s]-coords[3*t2];
  float dy=coords[3*s+1]-coords[3*t2+1];
  float dz=coords[3*s+2]-coords[3*t2+2];
  float d=dx*dx+dy*dy+dz*dz;
  float* o=&d_ea[(size_t)e*65];
  float x=d;
  #pragma unroll
  for(int i=0;i<32;i++){
    float sv,cv; sincosf(x,&sv,&cv);
    o[i]=sv; o[32+i]=cv;
    x*=0.5f;
  }
  o[64]=d;
}

// ---------------- per-layer: FA/FB = feats @ W1[part] (fp32 scalar) ----------------
__global__ void __launch_bounds__(256) k_fab(const float* __restrict__ keW1,int k){
  extern __shared__ float sm[];
  float* s_f = sm;               // 64*129
  float* s_w = sm + 64*129;      // 128*64
  int zc=blockIdx.z;
  const float* W = keW1 + (size_t)k*EINN*H1 + (size_t)(zc?DD:0)*H1;
  int jc0=blockIdx.x*64, n0=blockIdx.y*64;
  for(int i=threadIdx.x;i<64*DD;i+=256){int r=i>>7,c=i&127;int n=n0+r; s_f[r*129+c]= (n<NN)? d_feats[(size_t)n*DD+c]:0.f;}
  for(int i=threadIdx.x;i<DD*64;i+=256){int p=i>>6,c=i&63;int j=jc0+c; s_w[i]= (j<H1)? W[(size_t)p*H1+j]:0.f;}
  __syncthreads();
  int r0=(threadIdx.x>>4)*4, c0=(threadIdx.x&15)*4;
  float acc[4][4];
  #pragma unroll
  for(int i=0;i<4;i++){acc[i][0]=0;acc[i][1]=0;acc[i][2]=0;acc[i][3]=0;}
  for(int p=0;p<DD;p++){
    float4 w=*(float4*)(s_w+p*64+c0);
    #pragma unroll
    for(int i=0;i<4;i++){ float a=s_f[(r0+i)*129+p];
      acc[i][0]+=a*w.x; acc[i][1]+=a*w.y; acc[i][2]+=a*w.z; acc[i][3]+=a*w.w; }
  }
  float* OUT = zc? d_FB: d_FA;
  #pragma unroll
  for(int i=0;i<4;i++){int n=n0+r0+i; if(n<NN){
    #pragma unroll
    for(int j=0;j<4;j++){int jj=jc0+c0+j; if(jj<FASTRIDE) OUT[(size_t)n*FASTRIDE+jj]=acc[i][j];}
  }}
}

// ---------------- per-layer: fused edge MLP via tf32 MMA + LN + scatter ----------------
// grid 1250, 256 thr (8 warps); block = 128 edges
__global__ void __launch_bounds__(256,2) k_edge(const int* __restrict__ eidx,
   const float* __restrict__ keW1,const float* __restrict__ keb1,
   const float* __restrict__ keW2,const float* __restrict__ keb2,
   const float* __restrict__ keng,const float* __restrict__ kenb,int k){
  extern __shared__ float sm[];
  float* s_ea = sm;                    // 128*73
  float* s_w1 = s_ea + 128*73;         // 64*73  (W1 chunk transposed [n][k])
  float* s_h  = s_w1 + 64*73;          // 128*73
  float* s_w2 = s_h  + 128*73;         // 32*73  (W2 chunk transposed [n][k])
  float* s_b1 = s_w2 + 32*73;          // 64
  float* s_b2 = s_b1 + 64;             // 32
  float* s_g  = s_b2 + 32;             // 32
  float* s_bt = s_g + 32;              // 32
  int* s_dst = (int*)(s_bt+32);        // 128
  int* s_src = s_dst + 128;            // 128
  int tid=threadIdx.x;
  int e0=blockIdx.x*128;
  for(int i=tid;i<128*72;i+=256){ int r=i/72, c=i-r*72;
    s_ea[r*73+c] = (c<65)? tf32r(d_ea[(size_t)(e0+r)*65+c]) : 0.f; }
  if(tid<128){ s_dst[tid]=eidx[EE+e0+tid]; s_src[tid]=eidx[e0+tid]; }
  if(tid>=128 && tid<160){ int c=tid-128; s_b2[c]=keb2[k*MM+c]; s_g[c]=keng[k*MM+c]; s_bt[c]=kenb[k*MM+c]; }
  const float* W1c = keW1 + (size_t)k*EINN*H1 + (size_t)256*H1;
  const float* W2  = keW2 + (size_t)k*H1*MM;
  const float* B1  = keb1 + (size_t)k*H1;

  int w=tid>>5, l=tid&31, qr=l>>2, qc=l&3;
  int ra=w*16+qr, rb=ra+8;

  float4 c2[4];
  #pragma unroll
  for(int t=0;t<4;t++) c2[t]=make_float4(0.f,0.f,0.f,0.f);

  for(int ch=0; ch<11; ch++){
    int jc0=ch*64;
    __syncthreads();
    for(int i=tid;i<64*72;i+=256){ int kk=i>>6, n=i&63; int j=jc0+n;
      s_w1[n*73+kk] = (kk<65 && j<H1)? tf32r(W1c[(size_t)kk*H1+j]) : 0.f; }
    for(int i=tid;i<32*64;i+=256){ int kk=i>>5, n=i&31; int j=jc0+kk;
      s_w2[n*73+kk] = (j<H1)? tf32r(W2[(size_t)j*MM+n]) : 0.f; }
    if(tid<64){ int j=jc0+tid; s_b1[tid]=(j<H1)?B1[j]:0.f; }
    __syncthreads();

    // GEMM1: [128 x 72] @ [72 x 64] -> c1 (warp: 16 rows x 64 cols)
    float4 c1[8];
    #pragma unroll
    for(int t=0;t<8;t++) c1[t]=make_float4(0.f,0.f,0.f,0.f);
    #pragma unroll
    for(int ks=0;ks<9;ks++){
      int k0=ks*8;
      unsigned a0=__float_as_uint(s_ea[ra*73+k0+qc]);
      unsigned a1=__float_as_uint(s_ea[rb*73+k0+qc]);
      unsigned a2=__float_as_uint(s_ea[ra*73+k0+qc+4]);
      unsigned a3=__float_as_uint(s_ea[rb*73+k0+qc+4]);
      #pragma unroll
      for(int nt=0;nt<8;nt++){
        unsigned b0=__float_as_uint(s_w1[(nt*8+qr)*73+k0+qc]);
        unsigned b1v=__float_as_uint(s_w1[(nt*8+qr)*73+k0+qc+4]);
        mma8(c1[nt],a0,a1,a2,a3,b0,b1v);
      }
    }
    // epilogue: + bias + FA[dst] + FB[src], SiLU, -> s_h (tf32)
    {
      int nda=s_dst[ra], nsa=s_src[ra], ndb=s_dst[rb], nsb=s_src[rb];
      const float* FAa=d_FA+(size_t)nda*FASTRIDE+jc0;
      const float* FBa=d_FB+(size_t)nsa*FASTRIDE+jc0;
      const float* FAb=d_FA+(size_t)ndb*FASTRIDE+jc0;
      const float* FBb=d_FB+(size_t)nsb*FASTRIDE+jc0;
      #pragma unroll
      for(int nt=0;nt<8;nt++){
        int col0=nt*8+2*qc;
        float2 faa=*(const float2*)(FAa+col0);
        float2 fba=*(const float2*)(FBa+col0);
        float2 fab=*(const float2*)(FAb+col0);
        float2 fbb=*(const float2*)(FBb+col0);
        float b0=s_b1[col0], b1f=s_b1[col0+1];
        s_h[ra*73+col0]  =tf32r(siluf(c1[nt].x+b0 +faa.x+fba.x));
        s_h[ra*73+col0+1]=tf32r(siluf(c1[nt].y+b1f+faa.y+fba.y));
        s_h[rb*73+col0]  =tf32r(siluf(c1[nt].z+b0 +fab.x+fbb.x));
        s_h[rb*73+col0+1]=tf32r(siluf(c1[nt].w+b1f+fab.y+fbb.y));
      }
    }
    __syncthreads();
    // GEMM2 accumulate: [128 x 64] @ [64 x 32]
    #pragma unroll
    for(int ks=0;ks<8;ks++){
      int k0=ks*8;
      unsigned a0=__float_as_uint(s_h[ra*73+k0+qc]);
      unsigned a1=__float_as_uint(s_h[rb*73+k0+qc]);
      unsigned a2=__float_as_uint(s_h[ra*73+k0+qc+4]);
      unsigned a3=__float_as_uint(s_h[rb*73+k0+qc+4]);
      #pragma unroll
      for(int nt=0;nt<4;nt++){
        unsigned b0=__float_as_uint(s_w2[(nt*8+qr)*73+k0+qc]);
        unsigned b1v=__float_as_uint(s_w2[(nt*8+qr)*73+k0+qc+4]);
        mma8(c2[nt],a0,a1,a2,a3,b0,b1v);
      }
    }
  }
  // final: SiLU + LN(32) + scatter-add
  float va[8], vb[8];
  #pragma unroll
  for(int nt=0;nt<4;nt++){
    int col0=nt*8+2*qc;
    va[2*nt]  =siluf(c2[nt].x+s_b2[col0]);
    va[2*nt+1]=siluf(c2[nt].y+s_b2[col0+1]);
    vb[2*nt]  =siluf(c2[nt].z+s_b2[col0]);
    vb[2*nt+1]=siluf(c2[nt].w+s_b2[col0+1]);
  }
  float sa=0.f,ssa=0.f,sb=0.f,ssb=0.f;
  #pragma unroll
  for(int i=0;i<8;i++){ sa+=va[i]; ssa+=va[i]*va[i]; sb+=vb[i]; ssb+=vb[i]*vb[i]; }
  #pragma unroll
  for(int o=1;o<4;o<<=1){
    sa+=__shfl_xor_sync(0xffffffffu,sa,o); ssa+=__shfl_xor_sync(0xffffffffu,ssa,o);
    sb+=__shfl_xor_sync(0xffffffffu,sb,o); ssb+=__shfl_xor_sync(0xffffffffu,ssb,o);
  }
  float mua=sa*(1.f/MM), vara=ssa*(1.f/MM)-mua*mua, inva=rsqrtf(vara+1e-5f);
  float mub=sb*(1.f/MM), varb=ssb*(1.f/MM)-mub*mub, invb=rsqrtf(varb+1e-5f);
  float* pa=&d_msum[(size_t)s_dst[ra]*MM];
  float* pb=&d_msum[(size_t)s_dst[rb]*MM];
  #pragma unroll
  for(int nt=0;nt<4;nt++){
    int col0=nt*8+2*qc;
    atomicAdd(pa+col0,  (va[2*nt]  -mua)*inva*s_g[col0]  +s_bt[col0]);
    atomicAdd(pa+col0+1,(va[2*nt+1]-mua)*inva*s_g[col0+1]+s_bt[col0+1]);
    atomicAdd(pb+col0,  (vb[2*nt]  -mub)*invb*s_g[col0]  +s_bt[col0]);
    atomicAdd(pb+col0+1,(vb[2*nt+1]-mub)*invb*s_g[col0+1]+s_bt[col0+1]);
  }
}

// ---------------- per-layer: xcat = [LN(feats) | LN(msum/deg)] ----------------
__global__ void k_xcat(const float* __restrict__ keng,const float* __restrict__ kenb,
                       const float* __restrict__ kn1g,const float* __restrict__ kn1b,int k){
  int warp=threadIdx.x>>5, lane=threadIdx.x&31;
  int n=blockIdx.x*8+warp;
  const float* g1=kn1g+(size_t)k*128; const float* b1=kn1b+(size_t)k*128;
  float v[4],s=0.f,ss=0.f;
  #pragma unroll
  for(int i=0;i<4;i++){ float x=d_feats[(size_t)n*128+lane+32*i]; v[i]=x; s+=x; ss+=x*x; }
  #pragma unroll
  for(int o=16;o;o>>=1){ s+=__shfl_xor_sync(0xffffffffu,s,o); ss+=__shfl_xor_sync(0xffffffffu,ss,o); }
  float mu=s*(1.f/128), var=ss*(1.f/128)-mu*mu, inv=rsqrtf(var+1e-5f);
  #pragma unroll
  for(int i=0;i<4;i++){ int c=lane+32*i; d_xcat[(size_t)n*160+c]=(v[i]-mu)*inv*g1[c]+b1[c]; }
  float m=d_msum[(size_t)n*MM+lane]/fmaxf(d_deg[n],1.f);
  float s2=m, ss2=m*m;
  #pragma unroll
  for(int o=16;o;o>>=1){ s2+=__shfl_xor_sync(0xffffffffu,s2,o); ss2+=__shfl_xor_sync(0xffffffffu,ss2,o); }
  float mu2=s2*(1.f/MM), var2=ss2*(1.f/MM)-mu2*mu2, inv2=rsqrtf(var2+1e-5f);
  d_xcat[(size_t)n*160+128+lane]=(m-mu2)*inv2*keng[k*MM+lane]+kenb[k*MM+lane];
}

// ---------------- per-layer: fused node MLP + LN + residual (fp32 scalar) ----------------
__global__ void __launch_bounds__(256) k_node(const float* __restrict__ knW1,const float* __restrict__ knb1,
    const float* __restrict__ knW2,const float* __restrict__ knb2,
    const float* __restrict__ kn2g,const float* __restrict__ kn2b,int k){
  extern __shared__ float sm[];
  float* s_x=sm;            // 64*161=10304
  float* s_h=s_x+10304;     // 64*257=16448
  float* s_w=s_h+16448;     // 256*64=16384
  int tid=threadIdx.x;
  int n0=blockIdx.x*64;
  const float* W1=knW1+(size_t)k*160*256;
  const float* B1=knb1+(size_t)k*256;
  const float* W2=knW2+(size_t)k*256*128;
  const float* B2=knb2+(size_t)k*128;
  const float* G =kn2g+(size_t)k*128;
  const float* BT=kn2b+(size_t)k*128;
  for(int i=tid;i<64*160;i+=256){int r=i/160,c=i-r*160;int n=n0+r; s_x[r*161+c]= (n<NN)? d_xcat[(size_t)n*160+c]:0.f;}
  int r0=(tid>>4)*4, c0=(tid&15)*4;
  for(int oc=0;oc<4;oc++){
    __syncthreads();
    for(int i=tid;i<160*64;i+=256){int p=i>>6,c=i&63; s_w[i]=W1[(size_t)p*256+oc*64+c];}
    __syncthreads();
    float a4[4][4];
    #pragma unroll
    for(int i=0;i<4;i++){a4[i][0]=0;a4[i][1]=0;a4[i][2]=0;a4[i][3]=0;}
    for(int p=0;p<160;p++){
      float4 w=*(float4*)(s_w+p*64+c0);
      #pragma unroll
      for(int i=0;i<4;i++){ float a=s_x[(r0+i)*161+p];
        a4[i][0]+=a*w.x; a4[i][1]+=a*w.y; a4[i][2]+=a*w.z; a4[i][3]+=a*w.w; }
    }
    #pragma unroll
    for(int i=0;i<4;i++){
      #pragma unroll
      for(int j=0;j<4;j++){ int col=oc*64+c0+j;
        s_h[(r0+i)*257+col]=siluf(a4[i][j]+__ldg(&B1[col])); }
    }
  }
  __syncthreads();
  for(int oc=0;oc<2;oc++){
    if(oc) __syncthreads();
    for(int i=tid;i<256*64;i+=256){int p=i>>6,c=i&63; s_w[i]=W2[(size_t)p*128+oc*64+c];}
    __syncthreads();
    float a4[4][4];
    #pragma unroll
    for(int i=0;i<4;i++){a4[i][0]=0;a4[i][1]=0;a4[i][2]=0;a4[i][3]=0;}
    for(int p=0;p<256;p++){
      float4 w=*(float4*)(s_w+p*64+c0);
      #pragma unroll
      for(int i=0;i<4;i++){ float a=s_h[(r0+i)*257+p];
        a4[i][0]+=a*w.x; a4[i][1]+=a*w.y; a4[i][2]+=a*w.z; a4[i][3]+=a*w.w; }
    }
    #pragma unroll
    for(int i=0;i<4;i++){
      #pragma unroll
      for(int j=0;j<4;j++){ int col=oc*64+c0+j;
        s_x[(r0+i)*129+col]=a4[i][j]+__ldg(&B2[col]); }
    }
  }
  __syncthreads();
  int w=tid>>5, lane=tid&31;
  for(int rr=w; rr<64; rr+=8){
    int n=n0+rr;
    float v[4],s=0.f,ss=0.f;
    #pragma unroll
    for(int i=0;i<4;i++){ float x=s_x[rr*129+lane+32*i]; v[i]=x; s+=x; ss+=x*x; }
    #pragma unroll
    for(int o=16;o;o>>=1){ s+=__shfl_xor_sync(0xffffffffu,s,o); ss+=__shfl_xor_sync(0xffffffffu,ss,o); }
    float mu=s*(1.f/128), var=ss*(1.f/128)-mu*mu, inv=rsqrtf(var+1e-5f);
    if(n<NN){
      #pragma unroll
      for(int i=0;i<4;i++){ int c=lane+32*i;
        float nv=(v[i]-mu)*inv*G[c]+BT[c];
        float f=d_feats[(size_t)n*128+c]+nv;
        d_feats[(size_t)n*128+c]=f;
        d_fcat[(size_t)n*FH+(size_t)(k+1)*128+c]=f; }
    }
  }
}

// ---------------- head MLP ----------------
__global__ void __launch_bounds__(256) k_fnn0(const float* __restrict__ W,const float* __restrict__ b){
  __shared__ float s_a[64*65];
  __shared__ float s_w[64*64];
  int tid=threadIdx.x;
  int jc0=blockIdx.x*64, n0=blockIdx.y*64;
  int r0=(tid>>4)*4, c0=(tid&15)*4;
  float acc[4][4];
  #pragma unroll
  for(int i=0;i<4;i++){acc[i][0]=0;acc[i][1]=0;acc[i][2]=0;acc[i][3]=0;}
  for(int ch=0;ch<12;ch++){
    __syncthreads();
    for(int i=tid;i<64*64;i+=256){int r=i>>6,c=i&63;int n=n0+r; s_a[r*65+c]= (n<NN)? siluf(d_fcat[(size_t)n*FH+ch*64+c]) : 0.f;}
    for(int i=tid;i<64*64;i+=256){int p=i>>6,c=i&63; s_w[i]=W[(size_t)(ch*64+p)*F2 + jc0+c];}
    __syncthreads();
    for(int p=0;p<64;p++){
      float4 w=*(float4*)(s_w+p*64+c0);
      #pragma unroll
      for(int i=0;i<4;i++){ float a=s_a[(r0+i)*65+p];
        acc[i][0]+=a*w.x; acc[i][1]+=a*w.y; acc[i][2]+=a*w.z; acc[i][3]+=a*w.w; }
    }
  }
  #pragma unroll
  for(int i=0;i<4;i++){int n=n0+r0+i; if(n<NN){
    #pragma unroll
    for(int j=0;j<4;j++) d_f1[(size_t)n*F2+jc0+c0+j]=siluf(acc[i][j]+__ldg(&b[jc0+c0+j]));
  }}
}

__global__ void __launch_bounds__(256) k_fnn(const float* __restrict__ W,const float* __restrict__ b,int which){
  __shared__ float s_a[64*65];
  __shared__ float s_w[64*64];
  const float* fin = which? d_f2 : d_f1;
  float* fout = which? d_f1 : d_f2;
  int tid=threadIdx.x;
  int jc0=blockIdx.x*64, n0=blockIdx.y*64;
  int r0=(tid>>4)*4, c0=(tid&15)*4;
  float acc[4][4];
  #pragma unroll
  for(int i=0;i<4;i++){acc[i][0]=0;acc[i][1]=0;acc[i][2]=0;acc[i][3]=0;}
  for(int ch=0;ch<4;ch++){
    __syncthreads();
    for(int i=tid;i<64*64;i+=256){int r=i>>6,c=i&63;int n=n0+r; s_a[r*65+c]= (n<NN)? fin[(size_t)n*F2+ch*64+c] : 0.f;}
    for(int i=tid;i<64*64;i+=256){int p=i>>6,c=i&63; s_w[i]=W[(size_t)(ch*64+p)*F2 + jc0+c];}
    __syncthreads();
    for(int p=0;p<64;p++){
      float4 w=*(float4*)(s_w+p*64+c0);
      #pragma unroll
      for(int i=0;i<4;i++){ float a=s_a[(r0+i)*65+p];
        acc[i][0]+=a*w.x; acc[i][1]+=a*w.y; acc[i][2]+=a*w.z; acc[i][3]+=a*w.w; }
    }
  }
  #pragma unroll
  for(int i=0;i<4;i++){int n=n0+r0+i; if(n<NN){
    #pragma unroll
    for(int j=0;j<4;j++) fout[(size_t)n*F2+jc0+c0+j]=siluf(acc[i][j]+__ldg(&b[jc0+c0+j]));
  }}
}

__global__ void k_pool(const int* __restrict__ batch){
  int n=blockIdx.x; int c=threadIdx.x;
  int b=batch[n];
  atomicAdd(&d_gsum[b*F2+c], d_f1[(size_t)n*F2+c]);
  if(c==0) atomicAdd(&d_gcnt[b],1.f);
}

__global__ void k_final(const float* __restrict__ gW0,const float* __restrict__ gb0,
                        const float* __restrict__ gW1,const float* __restrict__ gb1,
                        const float* __restrict__ gW2,const float* __restrict__ gb2,
                        float* __restrict__ out){
  __shared__ float s_g[256], s_h[256], s_red[8];
  int b=blockIdx.x, t=threadIdx.x;
  float cnt=fmaxf(d_gcnt[b],1.f);
  s_g[t]=d_gsum[b*F2+t]/cnt;
  __syncthreads();
  float a=gb0[t];
  #pragma unroll 8
  for(int p=0;p<256;p++) a+=s_g[p]*gW0[p*256+t];
  s_h[t]=siluf(a);
  __syncthreads();
  a=gb1[t];
  #pragma unroll 8
  for(int p=0;p<256;p++) a+=s_h[p]*gW1[p*256+t];
  float h=siluf(a);
  float v=h*gW2[t];
  #pragma unroll
  for(int o=16;o;o>>=1) v+=__shfl_xor_sync(0xffffffffu,v,o);
  if((t&31)==0) s_red[t>>5]=v;
  __syncthreads();
  if(t==0){ float tot=0.f;
    #pragma unroll
    for(int i=0;i<8;i++) tot+=s_red[i];
    out[b]=tot+gb2[0]; }
}

// ---------------- host ----------------
extern "C" void kernel_launch(void* const* d_in, const int* in_sizes, int n_in,
                              void* d_out, int out_size){
  const float* coords =(const float*)d_in[0];
  const int*   atomids=(const int*)d_in[1];
  const int*   eidx   =(const int*)d_in[2];
  const int*   batch  =(const int*)d_in[3];
  int s = (in_sizes[4]==11*DD) ? 4 : 5;   // skip num_graphs scalar if present
  const float* emb =(const float*)d_in[s+0];
  const float* keW1=(const float*)d_in[s+1];
  const float* keb1=(const float*)d_in[s+2];
  const float* keW2=(const float*)d_in[s+3];
  const float* keb2=(const float*)d_in[s+4];
  const float* keng=(const float*)d_in[s+5];
  const float* kenb=(const float*)d_in[s+6];
  const float* kn1g=(const float*)d_in[s+7];
  const float* kn1b=(const float*)d_in[s+8];
  const float* knW1=(const float*)d_in[s+9];
  const float* knb1=(const float*)d_in[s+10];
  const float* knW2=(const float*)d_in[s+11];
  const float* knb2=(const float*)d_in[s+12];
  const float* kn2g=(const float*)d_in[s+13];
  const float* kn2b=(const float*)d_in[s+14];
  const float* fW0 =(const float*)d_in[s+15];
  const float* fb0 =(const float*)d_in[s+16];
  const float* fW1 =(const float*)d_in[s+17];
  const float* fb1 =(const float*)d_in[s+18];
  const float* fW2 =(const float*)d_in[s+19];
  const float* fb2 =(const float*)d_in[s+20];
  const float* gW0 =(const float*)d_in[s+21];
  const float* gb0 =(const float*)d_in[s+22];
  const float* gW1 =(const float*)d_in[s+23];
  const float* gb1 =(const float*)d_in[s+24];
  const float* gW2 =(const float*)d_in[s+25];
  const float* gb2 =(const float*)d_in[s+26];
  float* out=(float*)d_out;

  const int FAB_SM  = (64*129 + 128*64)*4;                        // 65792
  const int EDGE_SM = (128*73 + 64*73 + 128*73 + 32*73 + 64+32+32+32 + 256)*4; // 104448
  const int NODE_SM = (10304+16448+16384)*4;                      // 172544
  cudaFuncSetAttribute(k_fab,  cudaFuncAttributeMaxDynamicSharedMemorySize, FAB_SM);
  cudaFuncSetAttribute(k_edge, cudaFuncAttributeMaxDynamicSharedMemorySize, EDGE_SM);
  cudaFuncSetAttribute(k_node, cudaFuncAttributeMaxDynamicSharedMemorySize, NODE_SM);

  k_zero_init<<<65,256>>>();
  k_feats<<<NN,128>>>(emb,atomids);
  k_deg<<<EE/256,256>>>(eidx);
  k_ea<<<EE/256,256>>>(coords,eidx);
  for(int k=0;k<KK;k++){
    k_zero_msum<<<(NN*MM)/256,256>>>();
    k_fab<<<dim3(11,157,2),256,FAB_SM>>>(keW1,k);
    k_edge<<<EE/128,256,EDGE_SM>>>(eidx,keW1,keb1,keW2,keb2,keng,kenb,k);
    k_xcat<<<NN/8,256>>>(keng,kenb,kn1g,kn1b,k);
    k_node<<<157,256,NODE_SM>>>(knW1,knb1,knW2,knb2,kn2g,kn2b,k);
  }
  k_fnn0<<<dim3(4,157),256>>>(fW0,fb0);
  k_fnn<<<dim3(4,157),256>>>(fW1,fb1,0);
  k_fnn<<<dim3(4,157),256>>>(fW2,fb2,1);
  k_pool<<<NN,256>>>(batch);
  k_final<<<BB,256>>>(gW0,gb0,gW1,gb1,gW2,gb2,out);
}

// round 4
// speedup vs baseline: 1.4505x; 1.0820x over previous
#include <cuda_runtime.h>
#include <math.h>

#define NN 10000
#define EE 160000
#define BB 64
#define DD 128
#define MM 32
#define EINN 321
#define H1 642
#define KK 5
#define FH 768
#define F2 256
#define FASTRIDE 644

// ---------------- scratch (zero-initialized device globals) ----------------
__device__ float d_feats[NN*DD];
__device__ float d_ea[EE*65];
__device__ float d_deg[NN];
__device__ float d_FA[NN*FASTRIDE + 256];
__device__ float d_FB[NN*FASTRIDE + 256];
__device__ float d_msum[NN*MM];
__device__ float d_xcat[NN*160];
__device__ float d_fcat[NN*FH];
__device__ float d_f1[NN*F2];
__device__ float d_f2[NN*F2];
__device__ float d_gsum[BB*F2];
__device__ float d_gcnt[BB];

__device__ __forceinline__ float siluf(float x){ return x/(1.f+expf(-x)); }

__device__ __forceinline__ float tf32r(float x){
  float r; asm("cvt.rna.tf32.f32 %0,%1;" : "=f"(r) : "f"(x)); return r;
}
__device__ __forceinline__ void mma8(float4 &c, unsigned a0,unsigned a1,unsigned a2,unsigned a3,
                                     unsigned b0,unsigned b1){
  asm("mma.sync.aligned.m16n8k8.row.col.f32.tf32.tf32.f32 "
      "{%0,%1,%2,%3},{%4,%5,%6,%7},{%8,%9},{%0,%1,%2,%3};"
      : "+f"(c.x),"+f"(c.y),"+f"(c.z),"+f"(c.w)
      : "r"(a0),"r"(a1),"r"(a2),"r"(a3),"r"(b0),"r"(b1));
}
// permuted column index: fragment pair (k, k+4) contiguous
#define PERM(k) (((k)&3)*18 + ((k)>>2))
#define RS 72   // row stride (mod 32 == 8 -> conflict-free with qc*18)

// ---------------- init / zero kernels ----------------
__global__ void k_zero_init(){
  int i = blockIdx.x*256+threadIdx.x;
  if(i<NN) d_deg[i]=0.f;
  if(i<BB*F2) d_gsum[i]=0.f;
  if(i<BB) d_gcnt[i]=0.f;
}
__global__ void k_zero_msum(){
  int i = blockIdx.x*256+threadIdx.x;
  d_msum[i]=0.f;
}
__global__ void k_feats(const float* __restrict__ emb, const int* __restrict__ atomids){
  int n=blockIdx.x; int c=threadIdx.x;
  float v=emb[atomids[n]*DD+c];
  d_feats[n*DD+c]=v;
  d_fcat[(size_t)n*FH+c]=v;
}
__global__ void k_deg(const int* __restrict__ eidx){
  int e=blockIdx.x*256+threadIdx.x;
  atomicAdd(&d_deg[eidx[EE+e]],1.f);
}
__global__ void k_ea(const float* __restrict__ coords, const int* __restrict__ eidx){
  int e=blockIdx.x*256+threadIdx.x;
  int s=eidx[e], t2=eidx[EE+e];
  float dx=coords[3*s]-coords[3*t2];
  float dy=coords[3*s+1]-coords[3*t2+1];
  float dz=coords[3*s+2]-coords[3*t2+2];
  float d=dx*dx+dy*dy+dz*dz;
  float* o=&d_ea[(size_t)e*65];
  float x=d;
  #pragma unroll
  for(int i=0;i<32;i++){
    float sv,cv; sincosf(x,&sv,&cv);
    o[i]=sv; o[32+i]=cv;
    x*=0.5f;
  }
  o[64]=d;
}

// ---------------- per-layer: FA/FB = feats @ W1[part] (fp32 scalar) ----------------
__global__ void __launch_bounds__(256) k_fab(const float* __restrict__ keW1,int k){
  extern __shared__ float sm[];
  float* s_f = sm;               // 64*129
  float* s_w = sm + 64*129;      // 128*64
  int zc=blockIdx.z;
  const float* W = keW1 + (size_t)k*EINN*H1 + (size_t)(zc?DD:0)*H1;
  int jc0=blockIdx.x*64, n0=blockIdx.y*64;
  for(int i=threadIdx.x;i<64*DD;i+=256){int r=i>>7,c=i&127;int n=n0+r; s_f[r*129+c]= (n<NN)? d_feats[(size_t)n*DD+c]:0.f;}
  for(int i=threadIdx.x;i<DD*64;i+=256){int p=i>>6,c=i&63;int j=jc0+c; s_w[i]= (j<H1)? W[(size_t)p*H1+j]:0.f;}
  __syncthreads();
  int r0=(threadIdx.x>>4)*4, c0=(threadIdx.x&15)*4;
  float acc[4][4];
  #pragma unroll
  for(int i=0;i<4;i++){acc[i][0]=0;acc[i][1]=0;acc[i][2]=0;acc[i][3]=0;}
  for(int p=0;p<DD;p++){
    float4 w=*(float4*)(s_w+p*64+c0);
    #pragma unroll
    for(int i=0;i<4;i++){ float a=s_f[(r0+i)*129+p];
      acc[i][0]+=a*w.x; acc[i][1]+=a*w.y; acc[i][2]+=a*w.z; acc[i][3]+=a*w.w; }
  }
  float* OUT = zc? d_FB: d_FA;
  #pragma unroll
  for(int i=0;i<4;i++){int n=n0+r0+i; if(n<NN){
    #pragma unroll
    for(int j=0;j<4;j++){int jj=jc0+c0+j; if(jj<FASTRIDE) OUT[(size_t)n*FASTRIDE+jj]=acc[i][j];}
  }}
}

// ---------------- per-layer: fused edge MLP via tf32 MMA + LN + scatter ----------------
// grid 1250, 256 thr (8 warps); block = 128 edges
__global__ void __launch_bounds__(256,2) k_edge(const int* __restrict__ eidx,
   const float* __restrict__ keW1,const float* __restrict__ keb1,
   const float* __restrict__ keW2,const float* __restrict__ keb2,
   const float* __restrict__ keng,const float* __restrict__ kenb,int k){
  extern __shared__ float sm[];
  float* s_ea = sm;                    // 128*RS
  float* s_w1 = s_ea + 128*RS;         // 64*RS  (W1 chunk, [n][perm(k)])
  float* s_h  = s_w1 + 64*RS;          // 128*RS
  float* s_w2 = s_h  + 128*RS;         // 32*RS
  float* s_w1d= s_w2 + 32*RS;          // 64  (d-row of W1 chunk)
  float* s_d  = s_w1d + 64;            // 128 (d per edge)
  float* s_b1 = s_d + 128;             // 64
  float* s_b2 = s_b1 + 64;             // 32
  float* s_g  = s_b2 + 32;             // 32
  float* s_bt = s_g + 32;              // 32
  int* s_dst = (int*)(s_bt+32);        // 128
  int* s_src = s_dst + 128;            // 128
  int tid=threadIdx.x;
  int e0=blockIdx.x*128;
  for(int i=tid;i<128*64;i+=256){ int r=i>>6, c=i&63;
    s_ea[r*RS+PERM(c)] = tf32r(d_ea[(size_t)(e0+r)*65+c]); }
  if(tid<128){ s_dst[tid]=eidx[EE+e0+tid]; s_src[tid]=eidx[e0+tid];
               s_d[tid]=d_ea[(size_t)(e0+tid)*65+64]; }
  if(tid>=128 && tid<160){ int c=tid-128; s_b2[c]=keb2[k*MM+c]; s_g[c]=keng[k*MM+c]; s_bt[c]=kenb[k*MM+c]; }
  const float* W1c = keW1 + (size_t)k*EINN*H1 + (size_t)256*H1;
  const float* W2  = keW2 + (size_t)k*H1*MM;
  const float* B1  = keb1 + (size_t)k*H1;

  int w=tid>>5, l=tid&31, qr=l>>2, qc=l&3;
  int ra=w*16+qr, rb=ra+8;
  int aoff=qc*18;   // fragment column offset within permuted row

  float4 c2[4];
  #pragma unroll
  for(int t=0;t<4;t++) c2[t]=make_float4(0.f,0.f,0.f,0.f);

  for(int ch=0; ch<11; ch++){
    int jc0=ch*64;
    __syncthreads();
    // W1 chunk: 64 k-rows x 64 n-cols, permuted [n][perm(k)]
    for(int i=tid;i<64*64;i+=256){ int kk=i>>6, n=i&63; int j=jc0+n;
      s_w1[n*RS+PERM(kk)] = (j<H1)? tf32r(W1c[(size_t)kk*H1+j]) : 0.f; }
    // W2 chunk: 64 k-rows x 32 n-cols, permuted [n][perm(k)]
    for(int i=tid;i<64*32;i+=256){ int kk=i>>5, n=i&31; int j=jc0+kk;
      s_w2[n*RS+PERM(kk)] = (j<H1)? tf32r(W2[(size_t)j*MM+n]) : 0.f; }
    if(tid<64){ int j=jc0+tid; s_b1[tid]=(j<H1)?B1[j]:0.f;
                s_w1d[tid]=(j<H1)? W1c[(size_t)64*H1+j] : 0.f; }
    __syncthreads();

    // GEMM1: [128 x 64] @ [64 x 64]
    float4 c1[8];
    #pragma unroll
    for(int t=0;t<8;t++) c1[t]=make_float4(0.f,0.f,0.f,0.f);
    #pragma unroll
    for(int ks=0;ks<8;ks++){
      float2 A0=*(float2*)(s_ea+ra*RS+aoff+2*ks);
      float2 A1=*(float2*)(s_ea+rb*RS+aoff+2*ks);
      unsigned a0=__float_as_uint(A0.x), a2=__float_as_uint(A0.y);
      unsigned a1=__float_as_uint(A1.x), a3=__float_as_uint(A1.y);
      #pragma unroll
      for(int nt=0;nt<8;nt++){
        float2 Bv=*(float2*)(s_w1+(nt*8+qr)*RS+aoff+2*ks);
        mma8(c1[nt],a0,a1,a2,a3,__float_as_uint(Bv.x),__float_as_uint(Bv.y));
      }
    }
    // epilogue: + bias + d*W1d + FA[dst] + FB[src], SiLU -> s_h (permuted, tf32)
    {
      int nda=s_dst[ra], nsa=s_src[ra], ndb=s_dst[rb], nsb=s_src[rb];
      float da=s_d[ra], db=s_d[rb];
      const float* FAa=d_FA+(size_t)nda*FASTRIDE+jc0;
      const float* FBa=d_FA==d_FA? d_FB+(size_t)nsa*FASTRIDE+jc0 : 0;
      const float* FAb=d_FA+(size_t)ndb*FASTRIDE+jc0;
      const float* FBb=d_FB+(size_t)nsb*FASTRIDE+jc0;
      #pragma unroll
      for(int nt=0;nt<8;nt++){
        int col0=nt*8+2*qc;
        float2 faa=*(const float2*)(FAa+col0);
        float2 fba=*(const float2*)(FBa+col0);
        float2 fab=*(const float2*)(FAb+col0);
        float2 fbb=*(const float2*)(FBb+col0);
        float b0=s_b1[col0], b1f=s_b1[col0+1];
        float w0=s_w1d[col0], w1v=s_w1d[col0+1];
        int p0=((col0&3)*18) + (col0>>2);   // col0+1 -> p0+18
        s_h[ra*RS+p0]   =tf32r(siluf(c1[nt].x+b0 +da*w0 +faa.x+fba.x));
        s_h[ra*RS+p0+18]=tf32r(siluf(c1[nt].y+b1f+da*w1v+faa.y+fba.y));
        s_h[rb*RS+p0]   =tf32r(siluf(c1[nt].z+b0 +db*w0 +fab.x+fbb.x));
        s_h[rb*RS+p0+18]=tf32r(siluf(c1[nt].w+b1f+db*w1v+fab.y+fbb.y));
      }
    }
    __syncthreads();
    // GEMM2 accumulate: [128 x 64] @ [64 x 32]
    #pragma unroll
    for(int ks=0;ks<8;ks++){
      float2 A0=*(float2*)(s_h+ra*RS+aoff+2*ks);
      float2 A1=*(float2*)(s_h+rb*RS+aoff+2*ks);
      unsigned a0=__float_as_uint(A0.x), a2=__float_as_uint(A0.y);
      unsigned a1=__float_as_uint(A1.x), a3=__float_as_uint(A1.y);
      #pragma unroll
      for(int nt=0;nt<4;nt++){
        float2 Bv=*(float2*)(s_w2+(nt*8+qr)*RS+aoff+2*ks);
        mma8(c2[nt],a0,a1,a2,a3,__float_as_uint(Bv.x),__float_as_uint(Bv.y));
      }
    }
  }
  // final: SiLU + LN(32) + scatter-add
  float va[8], vb[8];
  #pragma unroll
  for(int nt=0;nt<4;nt++){
    int col0=nt*8+2*qc;
    va[2*nt]  =siluf(c2[nt].x+s_b2[col0]);
    va[2*nt+1]=siluf(c2[nt].y+s_b2[col0+1]);
    vb[2*nt]  =siluf(c2[nt].z+s_b2[col0]);
    vb[2*nt+1]=siluf(c2[nt].w+s_b2[col0+1]);
  }
  float sa=0.f,ssa=0.f,sb=0.f,ssb=0.f;
  #pragma unroll
  for(int i=0;i<8;i++){ sa+=va[i]; ssa+=va[i]*va[i]; sb+=vb[i]; ssb+=vb[i]*vb[i]; }
  #pragma unroll
  for(int o=1;o<4;o<<=1){
    sa+=__shfl_xor_sync(0xffffffffu,sa,o); ssa+=__shfl_xor_sync(0xffffffffu,ssa,o);
    sb+=__shfl_xor_sync(0xffffffffu,sb,o); ssb+=__shfl_xor_sync(0xffffffffu,ssb,o);
  }
  float mua=sa*(1.f/MM), vara=ssa*(1.f/MM)-mua*mua, inva=rsqrtf(vara+1e-5f);
  float mub=sb*(1.f/MM), varb=ssb*(1.f/MM)-mub*mub, invb=rsqrtf(varb+1e-5f);
  float* pa=&d_msum[(size_t)s_dst[ra]*MM];
  float* pb=&d_msum[(size_t)s_dst[rb]*MM];
  #pragma unroll
  for(int nt=0;nt<4;nt++){
    int col0=nt*8+2*qc;
    atomicAdd(pa+col0,  (va[2*nt]  -mua)*inva*s_g[col0]  +s_bt[col0]);
    atomicAdd(pa+col0+1,(va[2*nt+1]-mua)*inva*s_g[col0+1]+s_bt[col0+1]);
    atomicAdd(pb+col0,  (vb[2*nt]  -mub)*invb*s_g[col0]  +s_bt[col0]);
    atomicAdd(pb+col0+1,(vb[2*nt+1]-mub)*invb*s_g[col0+1]+s_bt[col0+1]);
  }
}

// ---------------- per-layer: xcat = [LN(feats) | LN(msum/deg)] ----------------
__global__ void k_xcat(const float* __restrict__ keng,const float* __restrict__ kenb,
                       const float* __restrict__ kn1g,const float* __restrict__ kn1b,int k){
  int warp=threadIdx.x>>5, lane=threadIdx.x&31;
  int n=blockIdx.x*8+warp;
  const float* g1=kn1g+(size_t)k*128; const float* b1=kn1b+(size_t)k*128;
  float v[4],s=0.f,ss=0.f;
  #pragma unroll
  for(int i=0;i<4;i++){ float x=d_feats[(size_t)n*128+lane+32*i]; v[i]=x; s+=x; ss+=x*x; }
  #pragma unroll
  for(int o=16;o;o>>=1){ s+=__shfl_xor_sync(0xffffffffu,s,o); ss+=__shfl_xor_sync(0xffffffffu,ss,o); }
  float mu=s*(1.f/128), var=ss*(1.f/128)-mu*mu, inv=rsqrtf(var+1e-5f);
  #pragma unroll
  for(int i=0;i<4;i++){ int c=lane+32*i; d_xcat[(size_t)n*160+c]=(v[i]-mu)*inv*g1[c]+b1[c]; }
  float m=d_msum[(size_t)n*MM+lane]/fmaxf(d_deg[n],1.f);
  float s2=m, ss2=m*m;
  #pragma unroll
  for(int o=16;o;o>>=1){ s2+=__shfl_xor_sync(0xffffffffu,s2,o); ss2+=__shfl_xor_sync(0xffffffffu,ss2,o); }
  float mu2=s2*(1.f/MM), var2=ss2*(1.f/MM)-mu2*mu2, inv2=rsqrtf(var2+1e-5f);
  d_xcat[(size_t)n*160+128+lane]=(m-mu2)*inv2*keng[k*MM+lane]+kenb[k*MM+lane];
}

// ---------------- per-layer: fused node MLP + LN + residual (fp32 scalar) ----------------
__global__ void __launch_bounds__(256) k_node(const float* __restrict__ knW1,const float* __restrict__ knb1,
    const float* __restrict__ knW2,const float* __restrict__ knb2,
    const float* __restrict__ kn2g,const float* __restrict__ kn2b,int k){
  extern __shared__ float sm[];
  float* s_x=sm;            // 64*161=10304
  float* s_h=s_x+10304;     // 64*257=16448
  float* s_w=s_h+16448;     // 256*64=16384
  int tid=threadIdx.x;
  int n0=blockIdx.x*64;
  const float* W1=knW1+(size_t)k*160*256;
  const float* B1=knb1+(size_t)k*256;
  const float* W2=knW2+(size_t)k*256*128;
  const float* B2=knb2+(size_t)k*128;
  const float* G =kn2g+(size_t)k*128;
  const float* BT=kn2b+(size_t)k*128;
  for(int i=tid;i<64*160;i+=256){int r=i/160,c=i-r*160;int n=n0+r; s_x[r*161+c]= (n<NN)? d_xcat[(size_t)n*160+c]:0.f;}
  int r0=(tid>>4)*4, c0=(tid&15)*4;
  for(int oc=0;oc<4;oc++){
    __syncthreads();
    for(int i=tid;i<160*64;i+=256){int p=i>>6,c=i&63; s_w[i]=W1[(size_t)p*256+oc*64+c];}
    __syncthreads();
    float a4[4][4];
    #pragma unroll
    for(int i=0;i<4;i++){a4[i][0]=0;a4[i][1]=0;a4[i][2]=0;a4[i][3]=0;}
    for(int p=0;p<160;p++){
      float4 w=*(float4*)(s_w+p*64+c0);
      #pragma unroll
      for(int i=0;i<4;i++){ float a=s_x[(r0+i)*161+p];
        a4[i][0]+=a*w.x; a4[i][1]+=a*w.y; a4[i][2]+=a*w.z; a4[i][3]+=a*w.w; }
    }
    #pragma unroll
    for(int i=0;i<4;i++){
      #pragma unroll
      for(int j=0;j<4;j++){ int col=oc*64+c0+j;
        s_h[(r0+i)*257+col]=siluf(a4[i][j]+__ldg(&B1[col])); }
    }
  }
  __syncthreads();
  for(int oc=0;oc<2;oc++){
    if(oc) __syncthreads();
    for(int i=tid;i<256*64;i+=256){int p=i>>6,c=i&63; s_w[i]=W2[(size_t)p*128+oc*64+c];}
    __syncthreads();
    float a4[4][4];
    #pragma unroll
    for(int i=0;i<4;i++){a4[i][0]=0;a4[i][1]=0;a4[i][2]=0;a4[i][3]=0;}
    for(int p=0;p<256;p++){
      float4 w=*(float4*)(s_w+p*64+c0);
      #pragma unroll
      for(int i=0;i<4;i++){ float a=s_h[(r0+i)*257+p];
        a4[i][0]+=a*w.x; a4[i][1]+=a*w.y; a4[i][2]+=a*w.z; a4[i][3]+=a*w.w; }
    }
    #pragma unroll
    for(int i=0;i<4;i++){
      #pragma unroll
      for(int j=0;j<4;j++){ int col=oc*64+c0+j;
        s_x[(r0+i)*129+col]=a4[i][j]+__ldg(&B2[col]); }
    }
  }
  __syncthreads();
  int w=tid>>5, lane=tid&31;
  for(int rr=w; rr<64; rr+=8){
    int n=n0+rr;
    float v[4],s=0.f,ss=0.f;
    #pragma unroll
    for(int i=0;i<4;i++){ float x=s_x[rr*129+lane+32*i]; v[i]=x; s+=x; ss+=x*x; }
    #pragma unroll
    for(int o=16;o;o>>=1){ s+=__shfl_xor_sync(0xffffffffu,s,o); ss+=__shfl_xor_sync(0xffffffffu,ss,o); }
    float mu=s*(1.f/128), var=ss*(1.f/128)-mu*mu, inv=rsqrtf(var+1e-5f);
    if(n<NN){
      #pragma unroll
      for(int i=0;i<4;i++){ int c=lane+32*i;
        float nv=(v[i]-mu)*inv*G[c]+BT[c];
        float f=d_feats[(size_t)n*128+c]+nv;
        d_feats[(size_t)n*128+c]=f;
        d_fcat[(size_t)n*FH+(size_t)(k+1)*128+c]=f; }
    }
  }
}

// ---------------- head MLP ----------------
__global__ void __launch_bounds__(256) k_fnn0(const float* __restrict__ W,const float* __restrict__ b){
  __shared__ float s_a[64*65];
  __shared__ float s_w[64*64];
  int tid=threadIdx.x;
  int jc0=blockIdx.x*64, n0=blockIdx.y*64;
  int r0=(tid>>4)*4, c0=(tid&15)*4;
  float acc[4][4];
  #pragma unroll
  for(int i=0;i<4;i++){acc[i][0]=0;acc[i][1]=0;acc[i][2]=0;acc[i][3]=0;}
  for(int ch=0;ch<12;ch++){
    __syncthreads();
    for(int i=tid;i<64*64;i+=256){int r=i>>6,c=i&63;int n=n0+r; s_a[r*65+c]= (n<NN)? siluf(d_fcat[(size_t)n*FH+ch*64+c]) : 0.f;}
    for(int i=tid;i<64*64;i+=256){int p=i>>6,c=i&63; s_w[i]=W[(size_t)(ch*64+p)*F2 + jc0+c];}
    __syncthreads();
    for(int p=0;p<64;p++){
      float4 w=*(float4*)(s_w+p*64+c0);
      #pragma unroll
      for(int i=0;i<4;i++){ float a=s_a[(r0+i)*65+p];
        acc[i][0]+=a*w.x; acc[i][1]+=a*w.y; acc[i][2]+=a*w.z; acc[i][3]+=a*w.w; }
    }
  }
  #pragma unroll
  for(int i=0;i<4;i++){int n=n0+r0+i; if(n<NN){
    #pragma unroll
    for(int j=0;j<4;j++) d_f1[(size_t)n*F2+jc0+c0+j]=siluf(acc[i][j]+__ldg(&b[jc0+c0+j]));
  }}
}

__global__ void __launch_bounds__(256) k_fnn(const float* __restrict__ W,const float* __restrict__ b,int which){
  __shared__ float s_a[64*65];
  __shared__ float s_w[64*64];
  const float* fin = which? d_f2 : d_f1;
  float* fout = which? d_f1 : d_f2;
  int tid=threadIdx.x;
  int jc0=blockIdx.x*64, n0=blockIdx.y*64;
  int r0=(tid>>4)*4, c0=(tid&15)*4;
  float acc[4][4];
  #pragma unroll
  for(int i=0;i<4;i++){acc[i][0]=0;acc[i][1]=0;acc[i][2]=0;acc[i][3]=0;}
  for(int ch=0;ch<4;ch++){
    __syncthreads();
    for(int i=tid;i<64*64;i+=256){int r=i>>6,c=i&63;int n=n0+r; s_a[r*65+c]= (n<NN)? fin[(size_t)n*F2+ch*64+c] : 0.f;}
    for(int i=tid;i<64*64;i+=256){int p=i>>6,c=i&63; s_w[i]=W[(size_t)(ch*64+p)*F2 + jc0+c];}
    __syncthreads();
    for(int p=0;p<64;p++){
      float4 w=*(float4*)(s_w+p*64+c0);
      #pragma unroll
      for(int i=0;i<4;i++){ float a=s_a[(r0+i)*65+p];
        acc[i][0]+=a*w.x; acc[i][1]+=a*w.y; acc[i][2]+=a*w.z; acc[i][3]+=a*w.w; }
    }
  }
  #pragma unroll
  for(int i=0;i<4;i++){int n=n0+r0+i; if(n<NN){
    #pragma unroll
    for(int j=0;j<4;j++) fout[(size_t)n*F2+jc0+c0+j]=siluf(acc[i][j]+__ldg(&b[jc0+c0+j]));
  }}
}

__global__ void k_pool(const int* __restrict__ batch){
  int n=blockIdx.x; int c=threadIdx.x;
  int b=batch[n];
  atomicAdd(&d_gsum[b*F2+c], d_f1[(size_t)n*F2+c]);
  if(c==0) atomicAdd(&d_gcnt[b],1.f);
}

__global__ void k_final(const float* __restrict__ gW0,const float* __restrict__ gb0,
                        const float* __restrict__ gW1,const float* __restrict__ gb1,
                        const float* __restrict__ gW2,const float* __restrict__ gb2,
                        float* __restrict__ out){
  __shared__ float s_g[256], s_h[256], s_red[8];
  int b=blockIdx.x, t=threadIdx.x;
  float cnt=fmaxf(d_gcnt[b],1.f);
  s_g[t]=d_gsum[b*F2+t]/cnt;
  __syncthreads();
  float a=gb0[t];
  #pragma unroll 8
  for(int p=0;p<256;p++) a+=s_g[p]*gW0[p*256+t];
  s_h[t]=siluf(a);
  __syncthreads();
  a=gb1[t];
  #pragma unroll 8
  for(int p=0;p<256;p++) a+=s_h[p]*gW1[p*256+t];
  float h=siluf(a);
  float v=h*gW2[t];
  #pragma unroll
  for(int o=16;o;o>>=1) v+=__shfl_xor_sync(0xffffffffu,v,o);
  if((t&31)==0) s_red[t>>5]=v;
  __syncthreads();
  if(t==0){ float tot=0.f;
    #pragma unroll
    for(int i=0;i<8;i++) tot+=s_red[i];
    out[b]=tot+gb2[0]; }
}

// ---------------- host ----------------
extern "C" void kernel_launch(void* const* d_in, const int* in_sizes, int n_in,
                              void* d_out, int out_size){
  const float* coords =(const float*)d_in[0];
  const int*   atomids=(const int*)d_in[1];
  const int*   eidx   =(const int*)d_in[2];
  const int*   batch  =(const int*)d_in[3];
  int s = (in_sizes[4]==11*DD) ? 4 : 5;   // skip num_graphs scalar if present
  const float* emb =(const float*)d_in[s+0];
  const float* keW1=(const float*)d_in[s+1];
  const float* keb1=(const float*)d_in[s+2];
  const float* keW2=(const float*)d_in[s+3];
  const float* keb2=(const float*)d_in[s+4];
  const float* keng=(const float*)d_in[s+5];
  const float* kenb=(const float*)d_in[s+6];
  const float* kn1g=(const float*)d_in[s+7];
  const float* kn1b=(const float*)d_in[s+8];
  const float* knW1=(const float*)d_in[s+9];
  const float* knb1=(const float*)d_in[s+10];
  const float* knW2=(const float*)d_in[s+11];
  const float* knb2=(const float*)d_in[s+12];
  const float* kn2g=(const float*)d_in[s+13];
  const float* kn2b=(const float*)d_in[s+14];
  const float* fW0 =(const float*)d_in[s+15];
  const float* fb0 =(const float*)d_in[s+16];
  const float* fW1 =(const float*)d_in[s+17];
  const float* fb1 =(const float*)d_in[s+18];
  const float* fW2 =(const float*)d_in[s+19];
  const float* fb2 =(const float*)d_in[s+20];
  const float* gW0 =(const float*)d_in[s+21];
  const float* gb0 =(const float*)d_in[s+22];
  const float* gW1 =(const float*)d_in[s+23];
  const float* gb1 =(const float*)d_in[s+24];
  const float* gW2 =(const float*)d_in[s+25];
  const float* gb2 =(const float*)d_in[s+26];
  float* out=(float*)d_out;

  const int FAB_SM  = (64*129 + 128*64)*4;                        // 65792
  const int EDGE_SM = (128*RS + 64*RS + 128*RS + 32*RS + 64 + 128 + 64 + 96 + 256)*4; // ~103KB
  const int NODE_SM = (10304+16448+16384)*4;                      // 172544
  cudaFuncSetAttribute(k_fab,  cudaFuncAttributeMaxDynamicSharedMemorySize, FAB_SM);
  cudaFuncSetAttribute(k_edge, cudaFuncAttributeMaxDynamicSharedMemorySize, EDGE_SM);
  cudaFuncSetAttribute(k_node, cudaFuncAttributeMaxDynamicSharedMemorySize, NODE_SM);

  k_zero_init<<<65,256>>>();
  k_feats<<<NN,128>>>(emb,atomids);
  k_deg<<<EE/256,256>>>(eidx);
  k_ea<<<EE/256,256>>>(coords,eidx);
  for(int k=0;k<KK;k++){
    k_zero_msum<<<(NN*MM)/256,256>>>();
    k_fab<<<dim3(11,157,2),256,FAB_SM>>>(keW1,k);
    k_edge<<<EE/128,256,EDGE_SM>>>(eidx,keW1,keb1,keW2,keb2,keng,kenb,k);
    k_xcat<<<NN/8,256>>>(keng,kenb,kn1g,kn1b,k);
    k_node<<<157,256,NODE_SM>>>(knW1,knb1,knW2,knb2,kn2g,kn2b,k);
  }
  k_fnn0<<<dim3(4,157),256>>>(fW0,fb0);
  k_fnn<<<dim3(4,157),256>>>(fW1,fb1,0);
  k_fnn<<<dim3(4,157),256>>>(fW2,fb2,1);
  k_pool<<<NN,256>>>(batch);
  k_final<<<BB,256>>>(gW0,gb0,gW1,gb1,gW2,gb2,out);
}

// round 5
// speedup vs baseline: 1.6303x; 1.1239x over previous
#include <cuda_runtime.h>
#include <math.h>

#define NN 10000
#define EE 160000
#define BB 64
#define DD 128
#define MM 32
#define EINN 321
#define H1 642
#define KK 5
#define FH 768
#define F2 256
#define FASTRIDE 644

// permuted column index: fragment pair (k, k+4) contiguous
#define PERM(k) (((k)&3)*18 + ((k)>>2))
#define RS 72   // row stride (mod 32 == 8 -> conflict-free with qc*18)

// ---------------- scratch (zero-initialized device globals) ----------------
__device__ float d_feats[NN*DD];
__device__ float d_eap[EE*RS];          // permuted tf32 edge attrs (sin/cos only)
__device__ float d_dcol[EE];            // fp32 squared distance per edge
__device__ float d_deg[NN];
__device__ float d_FA[NN*FASTRIDE + 256];
__device__ float d_FB[NN*FASTRIDE + 256];
__device__ float d_msum[NN*MM];
__device__ float d_xcat[NN*160];
__device__ float d_fcat[NN*FH];
__device__ float d_f1[NN*F2];
__device__ float d_f2[NN*F2];
__device__ float d_gsum[BB*F2];
__device__ float d_gcnt[BB];
__device__ float d_w1p[KK*11*64*RS];    // pre-permuted W1 chunks [k][ch][n][PERM(kk)]
__device__ float d_w2p[KK*11*32*RS];    // pre-permuted W2 chunks [k][ch][n][PERM(kk)]

__device__ __forceinline__ float siluf(float x){ return x/(1.f+expf(-x)); }

__device__ __forceinline__ float tf32r(float x){
  float r; asm("cvt.rna.tf32.f32 %0,%1;" : "=f"(r) : "f"(x)); return r;
}
__device__ __forceinline__ void mma8(float4 &c, unsigned a0,unsigned a1,unsigned a2,unsigned a3,
                                     unsigned b0,unsigned b1){
  asm("mma.sync.aligned.m16n8k8.row.col.f32.tf32.tf32.f32 "
      "{%0,%1,%2,%3},{%4,%5,%6,%7},{%8,%9},{%0,%1,%2,%3};"
      : "+f"(c.x),"+f"(c.y),"+f"(c.z),"+f"(c.w)
      : "r"(a0),"r"(a1),"r"(a2),"r"(a3),"r"(b0),"r"(b1));
}

// ---------------- init / zero kernels ----------------
__global__ void k_zero_init(){
  int i = blockIdx.x*256+threadIdx.x;
  if(i<NN) d_deg[i]=0.f;
  if(i<BB*F2) d_gsum[i]=0.f;
  if(i<BB) d_gcnt[i]=0.f;
}
__global__ void k_zero_msum(){
  int i = blockIdx.x*256+threadIdx.x;
  d_msum[i]=0.f;
}
__global__ void k_feats(const float* __restrict__ emb, const int* __restrict__ atomids){
  int n=blockIdx.x; int c=threadIdx.x;
  float v=emb[atomids[n]*DD+c];
  d_feats[n*DD+c]=v;
  d_fcat[(size_t)n*FH+c]=v;
}
__global__ void k_deg(const int* __restrict__ eidx){
  int e=blockIdx.x*256+threadIdx.x;
  atomicAdd(&d_deg[eidx[EE+e]],1.f);
}
__global__ void k_ea(const float* __restrict__ coords, const int* __restrict__ eidx){
  int e=blockIdx.x*256+threadIdx.x;
  int s=eidx[e], t2=eidx[EE+e];
  float dx=coords[3*s]-coords[3*t2];
  float dy=coords[3*s+1]-coords[3*t2+1];
  float dz=coords[3*s+2]-coords[3*t2+2];
  float d=dx*dx+dy*dy+dz*dz;
  float* o=&d_eap[(size_t)e*RS];
  float x=d;
  #pragma unroll
  for(int i=0;i<32;i++){
    float sv,cv; sincosf(x,&sv,&cv);
    o[PERM(i)]=tf32r(sv); o[PERM(32+i)]=tf32r(cv);
    x*=0.5f;
  }
  d_dcol[e]=d;
}

// ---------------- one-shot: pre-permute W1/W2 chunks for all layers ----------------
__global__ void k_wprep(const float* __restrict__ keW1, const float* __restrict__ keW2){
  int i = blockIdx.x*256+threadIdx.x;
  const int W1TOT = KK*11*64*64;
  const int W2TOT = KK*11*32*64;
  if(i < W1TOT){
    int kk=i&63; int n=(i>>6)&63; int ch=(i>>12)%11; int k=i/(64*64*11);
    int j=ch*64+n;
    float v = (j<H1)? tf32r(keW1[(size_t)k*EINN*H1 + (size_t)(256+kk)*H1 + j]) : 0.f;
    d_w1p[(size_t)(((k*11+ch)*64)+n)*RS + PERM(kk)] = v;
  } else if(i < W1TOT+W2TOT){
    int m=i-W1TOT;
    int kk=m&63; int n=(m>>6)&31; int ch=(m>>11)%11; int k=m/(32*64*11);
    int j=ch*64+kk;
    float v = (j<H1)? tf32r(keW2[(size_t)k*H1*MM + (size_t)j*MM + n]) : 0.f;
    d_w2p[(size_t)(((k*11+ch)*32)+n)*RS + PERM(kk)] = v;
  }
}

// ---------------- per-layer: FA/FB = feats @ W1[part] (fp32 scalar) ----------------
__global__ void __launch_bounds__(256) k_fab(const float* __restrict__ keW1,int k){
  extern __shared__ float sm[];
  float* s_f = sm;               // 64*129
  float* s_w = sm + 64*129;      // 128*64
  int zc=blockIdx.z;
  const float* W = keW1 + (size_t)k*EINN*H1 + (size_t)(zc?DD:0)*H1;
  int jc0=blockIdx.x*64, n0=blockIdx.y*64;
  for(int i=threadIdx.x;i<64*DD;i+=256){int r=i>>7,c=i&127;int n=n0+r; s_f[r*129+c]= (n<NN)? d_feats[(size_t)n*DD+c]:0.f;}
  for(int i=threadIdx.x;i<DD*64;i+=256){int p=i>>6,c=i&63;int j=jc0+c; s_w[i]= (j<H1)? W[(size_t)p*H1+j]:0.f;}
  __syncthreads();
  int r0=(threadIdx.x>>4)*4, c0=(threadIdx.x&15)*4;
  float acc[4][4];
  #pragma unroll
  for(int i=0;i<4;i++){acc[i][0]=0;acc[i][1]=0;acc[i][2]=0;acc[i][3]=0;}
  for(int p=0;p<DD;p++){
    float4 w=*(float4*)(s_w+p*64+c0);
    #pragma unroll
    for(int i=0;i<4;i++){ float a=s_f[(r0+i)*129+p];
      acc[i][0]+=a*w.x; acc[i][1]+=a*w.y; acc[i][2]+=a*w.z; acc[i][3]+=a*w.w; }
  }
  float* OUT = zc? d_FB: d_FA;
  #pragma unroll
  for(int i=0;i<4;i++){int n=n0+r0+i; if(n<NN){
    #pragma unroll
    for(int j=0;j<4;j++){int jj=jc0+c0+j; if(jj<FASTRIDE) OUT[(size_t)n*FASTRIDE+jj]=acc[i][j];}
  }}
}

// ---------------- per-layer: fused edge MLP via tf32 MMA + LN + scatter ----------------
// grid 1250, 256 thr (8 warps); block = 128 edges
__global__ void __launch_bounds__(256,2) k_edge(const int* __restrict__ eidx,
   const float* __restrict__ keW1,const float* __restrict__ keb1,
   const float* __restrict__ keb2,
   const float* __restrict__ keng,const float* __restrict__ kenb,int k){
  extern __shared__ float sm[];
  float* s_ea = sm;                    // 128*RS
  float* s_w1 = s_ea + 128*RS;         // 64*RS
  float* s_h  = s_w1 + 64*RS;          // 128*RS
  float* s_w2 = s_h  + 128*RS;         // 32*RS
  float* s_w1d= s_w2 + 32*RS;          // 64  (d-row of W1 chunk)
  float* s_d  = s_w1d + 64;            // 128 (d per edge)
  float* s_b1 = s_d + 128;             // 64
  float* s_b2 = s_b1 + 64;             // 32
  float* s_g  = s_b2 + 32;             // 32
  float* s_bt = s_g + 32;              // 32
  int* s_dst = (int*)(s_bt+32);        // 128
  int* s_src = s_dst + 128;            // 128
  int tid=threadIdx.x;
  int e0=blockIdx.x*128;
  // straight vector copy of pre-permuted ea
  {
    const float4* src=(const float4*)(d_eap + (size_t)e0*RS);
    float4* dst=(float4*)s_ea;
    #pragma unroll
    for(int i=0;i<9;i++) dst[tid+256*i]=src[tid+256*i];   // 128*72/4 = 2304 = 9*256
  }
  if(tid<128){ s_dst[tid]=eidx[EE+e0+tid]; s_src[tid]=eidx[e0+tid];
               s_d[tid]=d_dcol[e0+tid]; }
  if(tid>=128 && tid<160){ int c=tid-128; s_b2[c]=keb2[k*MM+c]; s_g[c]=keng[k*MM+c]; s_bt[c]=kenb[k*MM+c]; }
  const float* W1c = keW1 + (size_t)k*EINN*H1 + (size_t)256*H1;
  const float* B1  = keb1 + (size_t)k*H1;

  int w=tid>>5, l=tid&31, qr=l>>2, qc=l&3;
  int ra=w*16+qr, rb=ra+8;
  int aoff=qc*18;

  float4 c2[4];
  #pragma unroll
  for(int t=0;t<4;t++) c2[t]=make_float4(0.f,0.f,0.f,0.f);

  for(int ch=0; ch<11; ch++){
    int jc0=ch*64;
    __syncthreads();
    {
      const float4* w1src=(const float4*)(d_w1p + (size_t)((k*11+ch)*64)*RS);
      float4* w1dst=(float4*)s_w1;
      #pragma unroll
      for(int i=0;i<4;i++) w1dst[tid+256*i]=w1src[tid+256*i];   // 64*72/4=1152
      if(tid<128) w1dst[tid+1024]=w1src[tid+1024];
      const float4* w2src=(const float4*)(d_w2p + (size_t)((k*11+ch)*32)*RS);
      float4* w2dst=(float4*)s_w2;
      #pragma unroll
      for(int i=0;i<2;i++) w2dst[tid+256*i]=w2src[tid+256*i];   // 32*72/4=576
      if(tid<64) w2dst[tid+512]=w2src[tid+512];
      if(tid<64){ int j=jc0+tid; s_b1[tid]=(j<H1)?B1[j]:0.f;
                  s_w1d[tid]=(j<H1)? W1c[(size_t)64*H1+j] : 0.f; }
    }
    __syncthreads();

    // GEMM1: [128 x 64] @ [64 x 64]
    float4 c1[8];
    #pragma unroll
    for(int t=0;t<8;t++) c1[t]=make_float4(0.f,0.f,0.f,0.f);
    #pragma unroll
    for(int ks=0;ks<8;ks++){
      float2 A0=*(float2*)(s_ea+ra*RS+aoff+2*ks);
      float2 A1=*(float2*)(s_ea+rb*RS+aoff+2*ks);
      unsigned a0=__float_as_uint(A0.x), a2=__float_as_uint(A0.y);
      unsigned a1=__float_as_uint(A1.x), a3=__float_as_uint(A1.y);
      #pragma unroll
      for(int nt=0;nt<8;nt++){
        float2 Bv=*(float2*)(s_w1+(nt*8+qr)*RS+aoff+2*ks);
        mma8(c1[nt],a0,a1,a2,a3,__float_as_uint(Bv.x),__float_as_uint(Bv.y));
      }
    }
    // epilogue: + bias + d*W1d + FA[dst] + FB[src], SiLU -> s_h (permuted, tf32)
    {
      int nda=s_dst[ra], nsa=s_src[ra], ndb=s_dst[rb], nsb=s_src[rb];
      float da=s_d[ra], db=s_d[rb];
      const float* FAa=d_FA+(size_t)nda*FASTRIDE+jc0;
      const float* FBa=d_FB+(size_t)nsa*FASTRIDE+jc0;
      const float* FAb=d_FA+(size_t)ndb*FASTRIDE+jc0;
      const float* FBb=d_FB+(size_t)nsb*FASTRIDE+jc0;
      #pragma unroll
      for(int nt=0;nt<8;nt++){
        int col0=nt*8+2*qc;
        float2 faa=*(const float2*)(FAa+col0);
        float2 fba=*(const float2*)(FBa+col0);
        float2 fab=*(const float2*)(FAb+col0);
        float2 fbb=*(const float2*)(FBb+col0);
        float b0=s_b1[col0], b1f=s_b1[col0+1];
        float w0=s_w1d[col0], w1v=s_w1d[col0+1];
        int p0=((col0&3)*18) + (col0>>2);   // col0+1 -> p0+18
        s_h[ra*RS+p0]   =tf32r(siluf(c1[nt].x+b0 +da*w0 +faa.x+fba.x));
        s_h[ra*RS+p0+18]=tf32r(siluf(c1[nt].y+b1f+da*w1v+faa.y+fba.y));
        s_h[rb*RS+p0]   =tf32r(siluf(c1[nt].z+b0 +db*w0 +fab.x+fbb.x));
        s_h[rb*RS+p0+18]=tf32r(siluf(c1[nt].w+b1f+db*w1v+fab.y+fbb.y));
      }
    }
    __syncthreads();
    // GEMM2 accumulate: [128 x 64] @ [64 x 32]
    #pragma unroll
    for(int ks=0;ks<8;ks++){
      float2 A0=*(float2*)(s_h+ra*RS+aoff+2*ks);
      float2 A1=*(float2*)(s_h+rb*RS+aoff+2*ks);
      unsigned a0=__float_as_uint(A0.x), a2=__float_as_uint(A0.y);
      unsigned a1=__float_as_uint(A1.x), a3=__float_as_uint(A1.y);
      #pragma unroll
      for(int nt=0;nt<4;nt++){
        float2 Bv=*(float2*)(s_w2+(nt*8+qr)*RS+aoff+2*ks);
        mma8(c2[nt],a0,a1,a2,a3,__float_as_uint(Bv.x),__float_as_uint(Bv.y));
      }
    }
  }
  // final: SiLU + LN(32) + scatter-add
  float va[8], vb[8];
  #pragma unroll
  for(int nt=0;nt<4;nt++){
    int col0=nt*8+2*qc;
    va[2*nt]  =siluf(c2[nt].x+s_b2[col0]);
    va[2*nt+1]=siluf(c2[nt].y+s_b2[col0+1]);
    vb[2*nt]  =siluf(c2[nt].z+s_b2[col0]);
    vb[2*nt+1]=siluf(c2[nt].w+s_b2[col0+1]);
  }
  float sa=0.f,ssa=0.f,sb=0.f,ssb=0.f;
  #pragma unroll
  for(int i=0;i<8;i++){ sa+=va[i]; ssa+=va[i]*va[i]; sb+=vb[i]; ssb+=vb[i]*vb[i]; }
  #pragma unroll
  for(int o=1;o<4;o<<=1){
    sa+=__shfl_xor_sync(0xffffffffu,sa,o); ssa+=__shfl_xor_sync(0xffffffffu,ssa,o);
    sb+=__shfl_xor_sync(0xffffffffu,sb,o); ssb+=__shfl_xor_sync(0xffffffffu,ssb,o);
  }
  float mua=sa*(1.f/MM), vara=ssa*(1.f/MM)-mua*mua, inva=rsqrtf(vara+1e-5f);
  float mub=sb*(1.f/MM), varb=ssb*(1.f/MM)-mub*mub, invb=rsqrtf(varb+1e-5f);
  float* pa=&d_msum[(size_t)s_dst[ra]*MM];
  float* pb=&d_msum[(size_t)s_dst[rb]*MM];
  #pragma unroll
  for(int nt=0;nt<4;nt++){
    int col0=nt*8+2*qc;
    atomicAdd(pa+col0,  (va[2*nt]  -mua)*inva*s_g[col0]  +s_bt[col0]);
    atomicAdd(pa+col0+1,(va[2*nt+1]-mua)*inva*s_g[col0+1]+s_bt[col0+1]);
    atomicAdd(pb+col0,  (vb[2*nt]  -mub)*invb*s_g[col0]  +s_bt[col0]);
    atomicAdd(pb+col0+1,(vb[2*nt+1]-mub)*invb*s_g[col0+1]+s_bt[col0+1]);
  }
}

// ---------------- per-layer: xcat = [LN(feats) | LN(msum/deg)] ----------------
__global__ void k_xcat(const float* __restrict__ keng,const float* __restrict__ kenb,
                       const float* __restrict__ kn1g,const float* __restrict__ kn1b,int k){
  int warp=threadIdx.x>>5, lane=threadIdx.x&31;
  int n=blockIdx.x*8+warp;
  const float* g1=kn1g+(size_t)k*128; const float* b1=kn1b+(size_t)k*128;
  float v[4],s=0.f,ss=0.f;
  #pragma unroll
  for(int i=0;i<4;i++){ float x=d_feats[(size_t)n*128+lane+32*i]; v[i]=x; s+=x; ss+=x*x; }
  #pragma unroll
  for(int o=16;o;o>>=1){ s+=__shfl_xor_sync(0xffffffffu,s,o); ss+=__shfl_xor_sync(0xffffffffu,ss,o); }
  float mu=s*(1.f/128), var=ss*(1.f/128)-mu*mu, inv=rsqrtf(var+1e-5f);
  #pragma unroll
  for(int i=0;i<4;i++){ int c=lane+32*i; d_xcat[(size_t)n*160+c]=(v[i]-mu)*inv*g1[c]+b1[c]; }
  float m=d_msum[(size_t)n*MM+lane]/fmaxf(d_deg[n],1.f);
  float s2=m, ss2=m*m;
  #pragma unroll
  for(int o=16;o;o>>=1){ s2+=__shfl_xor_sync(0xffffffffu,s2,o); ss2+=__shfl_xor_sync(0xffffffffu,ss2,o); }
  float mu2=s2*(1.f/MM), var2=ss2*(1.f/MM)-mu2*mu2, inv2=rsqrtf(var2+1e-5f);
  d_xcat[(size_t)n*160+128+lane]=(m-mu2)*inv2*keng[k*MM+lane]+kenb[k*MM+lane];
}

// ---------------- per-layer: fused node MLP + LN + residual (fp32 scalar) ----------------
__global__ void __launch_bounds__(256) k_node(const float* __restrict__ knW1,const float* __restrict__ knb1,
    const float* __restrict__ knW2,const float* __restrict__ knb2,
    const float* __restrict__ kn2g,const float* __restrict__ kn2b,int k){
  extern __shared__ float sm[];
  float* s_x=sm;            // 64*161=10304
  float* s_h=s_x+10304;     // 64*257=16448
  float* s_w=s_h+16448;     // 256*64=16384
  int tid=threadIdx.x;
  int n0=blockIdx.x*64;
  const float* W1=knW1+(size_t)k*160*256;
  const float* B1=knb1+(size_t)k*256;
  const float* W2=knW2+(size_t)k*256*128;
  const float* B2=knb2+(size_t)k*128;
  const float* G =kn2g+(size_t)k*128;
  const float* BT=kn2b+(size_t)k*128;
  for(int i=tid;i<64*160;i+=256){int r=i/160,c=i-r*160;int n=n0+r; s_x[r*161+c]= (n<NN)? d_xcat[(size_t)n*160+c]:0.f;}
  int r0=(tid>>4)*4, c0=(tid&15)*4;
  for(int oc=0;oc<4;oc++){
    __syncthreads();
    for(int i=tid;i<160*64;i+=256){int p=i>>6,c=i&63; s_w[i]=W1[(size_t)p*256+oc*64+c];}
    __syncthreads();
    float a4[4][4];
    #pragma unroll
    for(int i=0;i<4;i++){a4[i][0]=0;a4[i][1]=0;a4[i][2]=0;a4[i][3]=0;}
    for(int p=0;p<160;p++){
      float4 w=*(float4*)(s_w+p*64+c0);
      #pragma unroll
      for(int i=0;i<4;i++){ float a=s_x[(r0+i)*161+p];
        a4[i][0]+=a*w.x; a4[i][1]+=a*w.y; a4[i][2]+=a*w.z; a4[i][3]+=a*w.w; }
    }
    #pragma unroll
    for(int i=0;i<4;i++){
      #pragma unroll
      for(int j=0;j<4;j++){ int col=oc*64+c0+j;
        s_h[(r0+i)*257+col]=siluf(a4[i][j]+__ldg(&B1[col])); }
    }
  }
  __syncthreads();
  for(int oc=0;oc<2;oc++){
    if(oc) __syncthreads();
    for(int i=tid;i<256*64;i+=256){int p=i>>6,c=i&63; s_w[i]=W2[(size_t)p*128+oc*64+c];}
    __syncthreads();
    float a4[4][4];
    #pragma unroll
    for(int i=0;i<4;i++){a4[i][0]=0;a4[i][1]=0;a4[i][2]=0;a4[i][3]=0;}
    for(int p=0;p<256;p++){
      float4 w=*(float4*)(s_w+p*64+c0);
      #pragma unroll
      for(int i=0;i<4;i++){ float a=s_h[(r0+i)*257+p];
        a4[i][0]+=a*w.x; a4[i][1]+=a*w.y; a4[i][2]+=a*w.z; a4[i][3]+=a*w.w; }
    }
    #pragma unroll
    for(int i=0;i<4;i++){
      #pragma unroll
      for(int j=0;j<4;j++){ int col=oc*64+c0+j;
        s_x[(r0+i)*129+col]=a4[i][j]+__ldg(&B2[col]); }
    }
  }
  __syncthreads();
  int w=tid>>5, lane=tid&31;
  for(int rr=w; rr<64; rr+=8){
    int n=n0+rr;
    float v[4],s=0.f,ss=0.f;
    #pragma unroll
    for(int i=0;i<4;i++){ float x=s_x[rr*129+lane+32*i]; v[i]=x; s+=x; ss+=x*x; }
    #pragma unroll
    for(int o=16;o;o>>=1){ s+=__shfl_xor_sync(0xffffffffu,s,o); ss+=__shfl_xor_sync(0xffffffffu,ss,o); }
    float mu=s*(1.f/128), var=ss*(1.f/128)-mu*mu, inv=rsqrtf(var+1e-5f);
    if(n<NN){
      #pragma unroll
      for(int i=0;i<4;i++){ int c=lane+32*i;
        float nv=(v[i]-mu)*inv*G[c]+BT[c];
        float f=d_feats[(size_t)n*128+c]+nv;
        d_feats[(size_t)n*128+c]=f;
        d_fcat[(size_t)n*FH+(size_t)(k+1)*128+c]=f; }
    }
  }
}

// ---------------- head MLP ----------------
__global__ void __launch_bounds__(256) k_fnn0(const float* __restrict__ W,const float* __restrict__ b){
  __shared__ float s_a[64*65];
  __shared__ float s_w[64*64];
  int tid=threadIdx.x;
  int jc0=blockIdx.x*64, n0=blockIdx.y*64;
  int r0=(tid>>4)*4, c0=(tid&15)*4;
  float acc[4][4];
  #pragma unroll
  for(int i=0;i<4;i++){acc[i][0]=0;acc[i][1]=0;acc[i][2]=0;acc[i][3]=0;}
  for(int ch=0;ch<12;ch++){
    __syncthreads();
    for(int i=tid;i<64*64;i+=256){int r=i>>6,c=i&63;int n=n0+r; s_a[r*65+c]= (n<NN)? siluf(d_fcat[(size_t)n*FH+ch*64+c]) : 0.f;}
    for(int i=tid;i<64*64;i+=256){int p=i>>6,c=i&63; s_w[i]=W[(size_t)(ch*64+p)*F2 + jc0+c];}
    __syncthreads();
    for(int p=0;p<64;p++){
      float4 w=*(float4*)(s_w+p*64+c0);
      #pragma unroll
      for(int i=0;i<4;i++){ float a=s_a[(r0+i)*65+p];
        acc[i][0]+=a*w.x; acc[i][1]+=a*w.y; acc[i][2]+=a*w.z; acc[i][3]+=a*w.w; }
    }
  }
  #pragma unroll
  for(int i=0;i<4;i++){int n=n0+r0+i; if(n<NN){
    #pragma unroll
    for(int j=0;j<4;j++) d_f1[(size_t)n*F2+jc0+c0+j]=siluf(acc[i][j]+__ldg(&b[jc0+c0+j]));
  }}
}

__global__ void __launch_bounds__(256) k_fnn(const float* __restrict__ W,const float* __restrict__ b,int which){
  __shared__ float s_a[64*65];
  __shared__ float s_w[64*64];
  const float* fin = which? d_f2 : d_f1;
  float* fout = which? d_f1 : d_f2;
  int tid=threadIdx.x;
  int jc0=blockIdx.x*64, n0=blockIdx.y*64;
  int r0=(tid>>4)*4, c0=(tid&15)*4;
  float acc[4][4];
  #pragma unroll
  for(int i=0;i<4;i++){acc[i][0]=0;acc[i][1]=0;acc[i][2]=0;acc[i][3]=0;}
  for(int ch=0;ch<4;ch++){
    __syncthreads();
    for(int i=tid;i<64*64;i+=256){int r=i>>6,c=i&63;int n=n0+r; s_a[r*65+c]= (n<NN)? fin[(size_t)n*F2+ch*64+c] : 0.f;}
    for(int i=tid;i<64*64;i+=256){int p=i>>6,c=i&63; s_w[i]=W[(size_t)(ch*64+p)*F2 + jc0+c];}
    __syncthreads();
    for(int p=0;p<64;p++){
      float4 w=*(float4*)(s_w+p*64+c0);
      #pragma unroll
      for(int i=0;i<4;i++){ float a=s_a[(r0+i)*65+p];
        acc[i][0]+=a*w.x; acc[i][1]+=a*w.y; acc[i][2]+=a*w.z; acc[i][3]+=a*w.w; }
    }
  }
  #pragma unroll
  for(int i=0;i<4;i++){int n=n0+r0+i; if(n<NN){
    #pragma unroll
    for(int j=0;j<4;j++) fout[(size_t)n*F2+jc0+c0+j]=siluf(acc[i][j]+__ldg(&b[jc0+c0+j]));
  }}
}

__global__ void k_pool(const int* __restrict__ batch){
  int n=blockIdx.x; int c=threadIdx.x;
  int b=batch[n];
  atomicAdd(&d_gsum[b*F2+c], d_f1[(size_t)n*F2+c]);
  if(c==0) atomicAdd(&d_gcnt[b],1.f);
}

__global__ void k_final(const float* __restrict__ gW0,const float* __restrict__ gb0,
                        const float* __restrict__ gW1,const float* __restrict__ gb1,
                        const float* __restrict__ gW2,const float* __restrict__ gb2,
                        float* __restrict__ out){
  __shared__ float s_g[256], s_h[256], s_red[8];
  int b=blockIdx.x, t=threadIdx.x;
  float cnt=fmaxf(d_gcnt[b],1.f);
  s_g[t]=d_gsum[b*F2+t]/cnt;
  __syncthreads();
  float a=gb0[t];
  #pragma unroll 8
  for(int p=0;p<256;p++) a+=s_g[p]*gW0[p*256+t];
  s_h[t]=siluf(a);
  __syncthreads();
  a=gb1[t];
  #pragma unroll 8
  for(int p=0;p<256;p++) a+=s_h[p]*gW1[p*256+t];
  float h=siluf(a);
  float v=h*gW2[t];
  #pragma unroll
  for(int o=16;o;o>>=1) v+=__shfl_xor_sync(0xffffffffu,v,o);
  if((t&31)==0) s_red[t>>5]=v;
  __syncthreads();
  if(t==0){ float tot=0.f;
    #pragma unroll
    for(int i=0;i<8;i++) tot+=s_red[i];
    out[b]=tot+gb2[0]; }
}

// ---------------- host ----------------
extern "C" void kernel_launch(void* const* d_in, const int* in_sizes, int n_in,
                              void* d_out, int out_size){
  const float* coords =(const float*)d_in[0];
  const int*   atomids=(const int*)d_in[1];
  const int*   eidx   =(const int*)d_in[2];
  const int*   batch  =(const int*)d_in[3];
  int s = (in_sizes[4]==11*DD) ? 4 : 5;   // skip num_graphs scalar if present
  const float* emb =(const float*)d_in[s+0];
  const float* keW1=(const float*)d_in[s+1];
  const float* keb1=(const float*)d_in[s+2];
  const float* keW2=(const float*)d_in[s+3];
  const float* keb2=(const float*)d_in[s+4];
  const float* keng=(const float*)d_in[s+5];
  const float* kenb=(const float*)d_in[s+6];
  const float* kn1g=(const float*)d_in[s+7];
  const float* kn1b=(const float*)d_in[s+8];
  const float* knW1=(const float*)d_in[s+9];
  const float* knb1=(const float*)d_in[s+10];
  const float* knW2=(const float*)d_in[s+11];
  const float* knb2=(const float*)d_in[s+12];
  const float* kn2g=(const float*)d_in[s+13];
  const float* kn2b=(const float*)d_in[s+14];
  const float* fW0 =(const float*)d_in[s+15];
  const float* fb0 =(const float*)d_in[s+16];
  const float* fW1 =(const float*)d_in[s+17];
  const float* fb1 =(const float*)d_in[s+18];
  const float* fW2 =(const float*)d_in[s+19];
  const float* fb2 =(const float*)d_in[s+20];
  const float* gW0 =(const float*)d_in[s+21];
  const float* gb0 =(const float*)d_in[s+22];
  const float* gW1 =(const float*)d_in[s+23];
  const float* gb1 =(const float*)d_in[s+24];
  const float* gW2 =(const float*)d_in[s+25];
  const float* gb2 =(const float*)d_in[s+26];
  float* out=(float*)d_out;

  const int FAB_SM  = (64*129 + 128*64)*4;                        // 65792
  const int EDGE_SM = (352*RS + 64 + 128 + 64 + 96 + 256)*4;      // 103808
  const int NODE_SM = (10304+16448+16384)*4;                      // 172544
  cudaFuncSetAttribute(k_fab,  cudaFuncAttributeMaxDynamicSharedMemorySize, FAB_SM);
  cudaFuncSetAttribute(k_edge, cudaFuncAttributeMaxDynamicSharedMemorySize, EDGE_SM);
  cudaFuncSetAttribute(k_node, cudaFuncAttributeMaxDynamicSharedMemorySize, NODE_SM);

  k_zero_init<<<65,256>>>();
  k_feats<<<NN,128>>>(emb,atomids);
  k_deg<<<EE/256,256>>>(eidx);
  k_ea<<<EE/256,256>>>(coords,eidx);
  k_wprep<<<1320,256>>>(keW1,keW2);   // 5*11*(64+32)*64 = 337920 elems
  for(int k=0;k<KK;k++){
    k_zero_msum<<<(NN*MM)/256,256>>>();
    k_fab<<<dim3(11,157,2),256,FAB_SM>>>(keW1,k);
    k_edge<<<EE/128,256,EDGE_SM>>>(eidx,keW1,keb1,keb2,keng,kenb,k);
    k_xcat<<<NN/8,256>>>(keng,kenb,kn1g,kn1b,k);
    k_node<<<157,256,NODE_SM>>>(knW1,knb1,knW2,knb2,kn2g,kn2b,k);
  }
  k_fnn0<<<dim3(4,157),256>>>(fW0,fb0);
  k_fnn<<<dim3(4,157),256>>>(fW1,fb1,0);
  k_fnn<<<dim3(4,157),256>>>(fW2,fb2,1);
  k_pool<<<NN,256>>>(batch);
  k_final<<<BB,256>>>(gW0,gb0,gW1,gb1,gW2,gb2,out);
}

// round 6
// speedup vs baseline: 1.7893x; 1.0976x over previous
#include <cuda_runtime.h>
#include <math.h>

#define NN 10000
#define EE 160000
#define BB 64
#define DD 128
#define MM 32
#define EINN 321
#define H1 642
#define KK 5
#define FH 768
#define F2 256
#define FASTRIDE 644

// permuted column index: fragment pair (k, k+4) contiguous
#define PERM(k) (((k)&3)*18 + ((k)>>2))
#define RS 72   // row stride (mod 32 == 8 -> conflict-free with qc*18)

// ---------------- scratch (zero-initialized device globals) ----------------
__device__ float d_feats[NN*DD];
__device__ float d_eap[EE*RS];          // permuted tf32 edge attrs (sin/cos only)
__device__ float d_dcol[EE];            // fp32 squared distance per edge
__device__ float d_deg[NN];
__device__ float d_FA[NN*FASTRIDE + 256];
__device__ float d_FB[NN*FASTRIDE + 256];
__device__ float d_msum[NN*MM];
__device__ float d_xcat[NN*160];
__device__ float d_fcat[NN*FH];
__device__ float d_f1[NN*F2];
__device__ float d_f2[NN*F2];
__device__ float d_gsum[BB*F2];
__device__ float d_gcnt[BB];
__device__ float d_w1p[KK*11*64*RS];    // pre-permuted W1 chunks [k][ch][n][PERM(kk)]
__device__ float d_w2p[KK*11*32*RS];    // pre-permuted W2 chunks [k][ch][n][PERM(kk)]

__device__ __forceinline__ float siluf(float x){
  return __fdividef(x, 1.f+__expf(-x));
}

__device__ __forceinline__ float tf32r(float x){
  float r; asm("cvt.rna.tf32.f32 %0,%1;" : "=f"(r) : "f"(x)); return r;
}
__device__ __forceinline__ void mma8(float4 &c, unsigned a0,unsigned a1,unsigned a2,unsigned a3,
                                     unsigned b0,unsigned b1){
  asm("mma.sync.aligned.m16n8k8.row.col.f32.tf32.tf32.f32 "
      "{%0,%1,%2,%3},{%4,%5,%6,%7},{%8,%9},{%0,%1,%2,%3};"
      : "+f"(c.x),"+f"(c.y),"+f"(c.z),"+f"(c.w)
      : "r"(a0),"r"(a1),"r"(a2),"r"(a3),"r"(b0),"r"(b1));
}

// ---------------- init / zero kernels ----------------
__global__ void k_zero_init(){
  int i = blockIdx.x*256+threadIdx.x;
  if(i<NN) d_deg[i]=0.f;
  if(i<BB*F2) d_gsum[i]=0.f;
  if(i<BB) d_gcnt[i]=0.f;
}
__global__ void k_zero_msum(){
  int i = blockIdx.x*256+threadIdx.x;
  d_msum[i]=0.f;
}
__global__ void k_feats(const float* __restrict__ emb, const int* __restrict__ atomids){
  int n=blockIdx.x; int c=threadIdx.x;
  float v=emb[atomids[n]*DD+c];
  d_feats[n*DD+c]=v;
  d_fcat[(size_t)n*FH+c]=v;
}
__global__ void k_deg(const int* __restrict__ eidx){
  int e=blockIdx.x*256+threadIdx.x;
  atomicAdd(&d_deg[eidx[EE+e]],1.f);
}
__global__ void k_ea(const float* __restrict__ coords, const int* __restrict__ eidx){
  int e=blockIdx.x*256+threadIdx.x;
  int s=eidx[e], t2=eidx[EE+e];
  float dx=coords[3*s]-coords[3*t2];
  float dy=coords[3*s+1]-coords[3*t2+1];
  float dz=coords[3*s+2]-coords[3*t2+2];
  float d=dx*dx+dy*dy+dz*dz;
  float* o=&d_eap[(size_t)e*RS];
  float x=d;
  #pragma unroll
  for(int i=0;i<32;i++){
    float sv,cv; __sincosf(x,&sv,&cv);
    o[PERM(i)]=tf32r(sv); o[PERM(32+i)]=tf32r(cv);
    x*=0.5f;
  }
  d_dcol[e]=d;
}

// ---------------- one-shot: pre-permute W1/W2 chunks for all layers ----------------
__global__ void k_wprep(const float* __restrict__ keW1, const float* __restrict__ keW2){
  int i = blockIdx.x*256+threadIdx.x;
  const int W1TOT = KK*11*64*64;
  const int W2TOT = KK*11*32*64;
  if(i < W1TOT){
    int kk=i&63; int n=(i>>6)&63; int ch=(i>>12)%11; int k=i/(64*64*11);
    int j=ch*64+n;
    float v = (j<H1)? tf32r(keW1[(size_t)k*EINN*H1 + (size_t)(256+kk)*H1 + j]) : 0.f;
    d_w1p[(size_t)(((k*11+ch)*64)+n)*RS + PERM(kk)] = v;
  } else if(i < W1TOT+W2TOT){
    int m=i-W1TOT;
    int kk=m&63; int n=(m>>6)&31; int ch=(m>>11)%11; int k=m/(32*64*11);
    int j=ch*64+kk;
    float v = (j<H1)? tf32r(keW2[(size_t)k*H1*MM + (size_t)j*MM + n]) : 0.f;
    d_w2p[(size_t)(((k*11+ch)*32)+n)*RS + PERM(kk)] = v;
  }
}

// ---------------- per-layer: FA/FB = feats @ W1[part] (fp32 scalar) ----------------
__global__ void __launch_bounds__(256) k_fab(const float* __restrict__ keW1,int k){
  extern __shared__ float sm[];
  float* s_f = sm;               // 64*129
  float* s_w = sm + 64*129;      // 128*64
  int zc=blockIdx.z;
  const float* W = keW1 + (size_t)k*EINN*H1 + (size_t)(zc?DD:0)*H1;
  int jc0=blockIdx.x*64, n0=blockIdx.y*64;
  for(int i=threadIdx.x;i<64*DD;i+=256){int r=i>>7,c=i&127;int n=n0+r; s_f[r*129+c]= (n<NN)? d_feats[(size_t)n*DD+c]:0.f;}
  for(int i=threadIdx.x;i<DD*64;i+=256){int p=i>>6,c=i&63;int j=jc0+c; s_w[i]= (j<H1)? W[(size_t)p*H1+j]:0.f;}
  __syncthreads();
  int r0=(threadIdx.x>>4)*4, c0=(threadIdx.x&15)*4;
  float acc[4][4];
  #pragma unroll
  for(int i=0;i<4;i++){acc[i][0]=0;acc[i][1]=0;acc[i][2]=0;acc[i][3]=0;}
  for(int p=0;p<DD;p++){
    float4 w=*(float4*)(s_w+p*64+c0);
    #pragma unroll
    for(int i=0;i<4;i++){ float a=s_f[(r0+i)*129+p];
      acc[i][0]+=a*w.x; acc[i][1]+=a*w.y; acc[i][2]+=a*w.z; acc[i][3]+=a*w.w; }
  }
  float* OUT = zc? d_FB: d_FA;
  #pragma unroll
  for(int i=0;i<4;i++){int n=n0+r0+i; if(n<NN){
    #pragma unroll
    for(int j=0;j<4;j++){int jj=jc0+c0+j; if(jj<FASTRIDE) OUT[(size_t)n*FASTRIDE+jj]=acc[i][j];}
  }}
}

// ---------------- per-layer: fused edge MLP via tf32 MMA + LN + scatter ----------------
// grid 1250, 256 thr (8 warps); block = 128 edges
__global__ void __launch_bounds__(256,2) k_edge(const int* __restrict__ eidx,
   const float* __restrict__ keW1,const float* __restrict__ keb1,
   const float* __restrict__ keb2,
   const float* __restrict__ keng,const float* __restrict__ kenb,int k){
  extern __shared__ float sm[];
  float* s_ea = sm;                    // 128*RS
  float* s_w1 = s_ea + 128*RS;         // 64*RS
  float* s_h  = s_w1 + 64*RS;          // 128*RS
  float* s_w2 = s_h  + 128*RS;         // 32*RS
  float* s_w1d= s_w2 + 32*RS;          // 64  (d-row of W1 chunk)
  float* s_d  = s_w1d + 64;            // 128 (d per edge)
  float* s_b1 = s_d + 128;             // 64
  float* s_b2 = s_b1 + 64;             // 32
  float* s_g  = s_b2 + 32;             // 32
  float* s_bt = s_g + 32;              // 32
  int* s_dst = (int*)(s_bt+32);        // 128
  int* s_src = s_dst + 128;            // 128
  int tid=threadIdx.x;
  int e0=blockIdx.x*128;
  // straight vector copy of pre-permuted ea
  {
    const float4* src=(const float4*)(d_eap + (size_t)e0*RS);
    float4* dst=(float4*)s_ea;
    #pragma unroll
    for(int i=0;i<9;i++) dst[tid+256*i]=src[tid+256*i];   // 128*72/4 = 2304 = 9*256
  }
  if(tid<128){ s_dst[tid]=eidx[EE+e0+tid]; s_src[tid]=eidx[e0+tid];
               s_d[tid]=d_dcol[e0+tid]; }
  if(tid>=128 && tid<160){ int c=tid-128; s_b2[c]=keb2[k*MM+c]; s_g[c]=keng[k*MM+c]; s_bt[c]=kenb[k*MM+c]; }
  const float* W1c = keW1 + (size_t)k*EINN*H1 + (size_t)256*H1;
  const float* B1  = keb1 + (size_t)k*H1;

  int w=tid>>5, l=tid&31, qr=l>>2, qc=l&3;
  int ra=w*16+qr, rb=ra+8;
  int aoff=qc*18;

  float4 c2[4];
  #pragma unroll
  for(int t=0;t<4;t++) c2[t]=make_float4(0.f,0.f,0.f,0.f);

  for(int ch=0; ch<11; ch++){
    int jc0=ch*64;
    __syncthreads();
    {
      const float4* w1src=(const float4*)(d_w1p + (size_t)((k*11+ch)*64)*RS);
      float4* w1dst=(float4*)s_w1;
      #pragma unroll
      for(int i=0;i<4;i++) w1dst[tid+256*i]=w1src[tid+256*i];   // 64*72/4=1152
      if(tid<128) w1dst[tid+1024]=w1src[tid+1024];
      const float4* w2src=(const float4*)(d_w2p + (size_t)((k*11+ch)*32)*RS);
      float4* w2dst=(float4*)s_w2;
      #pragma unroll
      for(int i=0;i<2;i++) w2dst[tid+256*i]=w2src[tid+256*i];   // 32*72/4=576
      if(tid<64) w2dst[tid+512]=w2src[tid+512];
      if(tid<64){ int j=jc0+tid; s_b1[tid]=(j<H1)?B1[j]:0.f;
                  s_w1d[tid]=(j<H1)? W1c[(size_t)64*H1+j] : 0.f; }
    }
    __syncthreads();

    // GEMM1: [128 x 64] @ [64 x 64]
    float4 c1[8];
    #pragma unroll
    for(int t=0;t<8;t++) c1[t]=make_float4(0.f,0.f,0.f,0.f);
    #pragma unroll
    for(int ks=0;ks<8;ks++){
      float2 A0=*(float2*)(s_ea+ra*RS+aoff+2*ks);
      float2 A1=*(float2*)(s_ea+rb*RS+aoff+2*ks);
      unsigned a0=__float_as_uint(A0.x), a2=__float_as_uint(A0.y);
      unsigned a1=__float_as_uint(A1.x), a3=__float_as_uint(A1.y);
      #pragma unroll
      for(int nt=0;nt<8;nt++){
        float2 Bv=*(float2*)(s_w1+(nt*8+qr)*RS+aoff+2*ks);
        mma8(c1[nt],a0,a1,a2,a3,__float_as_uint(Bv.x),__float_as_uint(Bv.y));
      }
    }
    // epilogue: + bias + d*W1d + FA[dst] + FB[src], SiLU -> s_h (permuted, tf32)
    {
      int nda=s_dst[ra], nsa=s_src[ra], ndb=s_dst[rb], nsb=s_src[rb];
      float da=s_d[ra], db=s_d[rb];
      const float* FAa=d_FA+(size_t)nda*FASTRIDE+jc0;
      const float* FBa=d_FB+(size_t)nsa*FASTRIDE+jc0;
      const float* FAb=d_FA+(size_t)ndb*FASTRIDE+jc0;
      const float* FBb=d_FB+(size_t)nsb*FASTRIDE+jc0;
      #pragma unroll
      for(int nt=0;nt<8;nt++){
        int col0=nt*8+2*qc;
        float2 faa=*(const float2*)(FAa+col0);
        float2 fba=*(const float2*)(FBa+col0);
        float2 fab=*(const float2*)(FAb+col0);
        float2 fbb=*(const float2*)(FBb+col0);
        float b0=s_b1[col0], b1f=s_b1[col0+1];
        float w0=s_w1d[col0], w1v=s_w1d[col0+1];
        int p0=((col0&3)*18) + (col0>>2);   // col0+1 -> p0+18
        s_h[ra*RS+p0]   =tf32r(siluf(c1[nt].x+b0 +da*w0 +faa.x+fba.x));
        s_h[ra*RS+p0+18]=tf32r(siluf(c1[nt].y+b1f+da*w1v+faa.y+fba.y));
        s_h[rb*RS+p0]   =tf32r(siluf(c1[nt].z+b0 +db*w0 +fab.x+fbb.x));
        s_h[rb*RS+p0+18]=tf32r(siluf(c1[nt].w+b1f+db*w1v+fab.y+fbb.y));
      }
    }
    __syncthreads();
    // GEMM2 accumulate: [128 x 64] @ [64 x 32]
    #pragma unroll
    for(int ks=0;ks<8;ks++){
      float2 A0=*(float2*)(s_h+ra*RS+aoff+2*ks);
      float2 A1=*(float2*)(s_h+rb*RS+aoff+2*ks);
      unsigned a0=__float_as_uint(A0.x), a2=__float_as_uint(A0.y);
      unsigned a1=__float_as_uint(A1.x), a3=__float_as_uint(A1.y);
      #pragma unroll
      for(int nt=0;nt<4;nt++){
        float2 Bv=*(float2*)(s_w2+(nt*8+qr)*RS+aoff+2*ks);
        mma8(c2[nt],a0,a1,a2,a3,__float_as_uint(Bv.x),__float_as_uint(Bv.y));
      }
    }
  }
  // final: SiLU + LN(32) + scatter-add
  float va[8], vb[8];
  #pragma unroll
  for(int nt=0;nt<4;nt++){
    int col0=nt*8+2*qc;
    va[2*nt]  =siluf(c2[nt].x+s_b2[col0]);
    va[2*nt+1]=siluf(c2[nt].y+s_b2[col0+1]);
    vb[2*nt]  =siluf(c2[nt].z+s_b2[col0]);
    vb[2*nt+1]=siluf(c2[nt].w+s_b2[col0+1]);
  }
  float sa=0.f,ssa=0.f,sb=0.f,ssb=0.f;
  #pragma unroll
  for(int i=0;i<8;i++){ sa+=va[i]; ssa+=va[i]*va[i]; sb+=vb[i]; ssb+=vb[i]*vb[i]; }
  #pragma unroll
  for(int o=1;o<4;o<<=1){
    sa+=__shfl_xor_sync(0xffffffffu,sa,o); ssa+=__shfl_xor_sync(0xffffffffu,ssa,o);
    sb+=__shfl_xor_sync(0xffffffffu,sb,o); ssb+=__shfl_xor_sync(0xffffffffu,ssb,o);
  }
  float mua=sa*(1.f/MM), vara=ssa*(1.f/MM)-mua*mua, inva=rsqrtf(vara+1e-5f);
  float mub=sb*(1.f/MM), varb=ssb*(1.f/MM)-mub*mub, invb=rsqrtf(varb+1e-5f);
  float* pa=&d_msum[(size_t)s_dst[ra]*MM];
  float* pb=&d_msum[(size_t)s_dst[rb]*MM];
  #pragma unroll
  for(int nt=0;nt<4;nt++){
    int col0=nt*8+2*qc;
    atomicAdd(pa+col0,  (va[2*nt]  -mua)*inva*s_g[col0]  +s_bt[col0]);
    atomicAdd(pa+col0+1,(va[2*nt+1]-mua)*inva*s_g[col0+1]+s_bt[col0+1]);
    atomicAdd(pb+col0,  (vb[2*nt]  -mub)*invb*s_g[col0]  +s_bt[col0]);
    atomicAdd(pb+col0+1,(vb[2*nt+1]-mub)*invb*s_g[col0+1]+s_bt[col0+1]);
  }
}

// ---------------- per-layer: xcat = [LN(feats) | LN(msum/deg)] ----------------
__global__ void k_xcat(const float* __restrict__ keng,const float* __restrict__ kenb,
                       const float* __restrict__ kn1g,const float* __restrict__ kn1b,int k){
  int warp=threadIdx.x>>5, lane=threadIdx.x&31;
  int n=blockIdx.x*8+warp;
  const float* g1=kn1g+(size_t)k*128; const float* b1=kn1b+(size_t)k*128;
  float v[4],s=0.f,ss=0.f;
  #pragma unroll
  for(int i=0;i<4;i++){ float x=d_feats[(size_t)n*128+lane+32*i]; v[i]=x; s+=x; ss+=x*x; }
  #pragma unroll
  for(int o=16;o;o>>=1){ s+=__shfl_xor_sync(0xffffffffu,s,o); ss+=__shfl_xor_sync(0xffffffffu,ss,o); }
  float mu=s*(1.f/128), var=ss*(1.f/128)-mu*mu, inv=rsqrtf(var+1e-5f);
  #pragma unroll
  for(int i=0;i<4;i++){ int c=lane+32*i; d_xcat[(size_t)n*160+c]=(v[i]-mu)*inv*g1[c]+b1[c]; }
  float m=d_msum[(size_t)n*MM+lane]/fmaxf(d_deg[n],1.f);
  float s2=m, ss2=m*m;
  #pragma unroll
  for(int o=16;o;o>>=1){ s2+=__shfl_xor_sync(0xffffffffu,s2,o); ss2+=__shfl_xor_sync(0xffffffffu,ss2,o); }
  float mu2=s2*(1.f/MM), var2=ss2*(1.f/MM)-mu2*mu2, inv2=rsqrtf(var2+1e-5f);
  d_xcat[(size_t)n*160+128+lane]=(m-mu2)*inv2*keng[k*MM+lane]+kenb[k*MM+lane];
}

// ---------------- per-layer: fused node MLP + LN + residual (fp32 scalar) ----------------
__global__ void __launch_bounds__(256) k_node(const float* __restrict__ knW1,const float* __restrict__ knb1,
    const float* __restrict__ knW2,const float* __restrict__ knb2,
    const float* __restrict__ kn2g,const float* __restrict__ kn2b,int k){
  extern __shared__ float sm[];
  float* s_x=sm;            // 64*161=10304
  float* s_h=s_x+10304;     // 64*257=16448
  float* s_w=s_h+16448;     // 256*64=16384
  int tid=threadIdx.x;
  int n0=blockIdx.x*64;
  const float* W1=knW1+(size_t)k*160*256;
  const float* B1=knb1+(size_t)k*256;
  const float* W2=knW2+(size_t)k*256*128;
  const float* B2=knb2+(size_t)k*128;
  const float* G =kn2g+(size_t)k*128;
  const float* BT=kn2b+(size_t)k*128;
  for(int i=tid;i<64*160;i+=256){int r=i/160,c=i-r*160;int n=n0+r; s_x[r*161+c]= (n<NN)? d_xcat[(size_t)n*160+c]:0.f;}
  int r0=(tid>>4)*4, c0=(tid&15)*4;
  for(int oc=0;oc<4;oc++){
    __syncthreads();
    for(int i=tid;i<160*64;i+=256){int p=i>>6,c=i&63; s_w[i]=W1[(size_t)p*256+oc*64+c];}
    __syncthreads();
    float a4[4][4];
    #pragma unroll
    for(int i=0;i<4;i++){a4[i][0]=0;a4[i][1]=0;a4[i][2]=0;a4[i][3]=0;}
    for(int p=0;p<160;p++){
      float4 w=*(float4*)(s_w+p*64+c0);
      #pragma unroll
      for(int i=0;i<4;i++){ float a=s_x[(r0+i)*161+p];
        a4[i][0]+=a*w.x; a4[i][1]+=a*w.y; a4[i][2]+=a*w.z; a4[i][3]+=a*w.w; }
    }
    #pragma unroll
    for(int i=0;i<4;i++){
      #pragma unroll
      for(int j=0;j<4;j++){ int col=oc*64+c0+j;
        s_h[(r0+i)*257+col]=siluf(a4[i][j]+__ldg(&B1[col])); }
    }
  }
  __syncthreads();
  for(int oc=0;oc<2;oc++){
    if(oc) __syncthreads();
    for(int i=tid;i<256*64;i+=256){int p=i>>6,c=i&63; s_w[i]=W2[(size_t)p*128+oc*64+c];}
    __syncthreads();
    float a4[4][4];
    #pragma unroll
    for(int i=0;i<4;i++){a4[i][0]=0;a4[i][1]=0;a4[i][2]=0;a4[i][3]=0;}
    for(int p=0;p<256;p++){
      float4 w=*(float4*)(s_w+p*64+c0);
      #pragma unroll
      for(int i=0;i<4;i++){ float a=s_h[(r0+i)*257+p];
        a4[i][0]+=a*w.x; a4[i][1]+=a*w.y; a4[i][2]+=a*w.z; a4[i][3]+=a*w.w; }
    }
    #pragma unroll
    for(int i=0;i<4;i++){
      #pragma unroll
      for(int j=0;j<4;j++){ int col=oc*64+c0+j;
        s_x[(r0+i)*129+col]=a4[i][j]+__ldg(&B2[col]); }
    }
  }
  __syncthreads();
  int w=tid>>5, lane=tid&31;
  for(int rr=w; rr<64; rr+=8){
    int n=n0+rr;
    float v[4],s=0.f,ss=0.f;
    #pragma unroll
    for(int i=0;i<4;i++){ float x=s_x[rr*129+lane+32*i]; v[i]=x; s+=x; ss+=x*x; }
    #pragma unroll
    for(int o=16;o;o>>=1){ s+=__shfl_xor_sync(0xffffffffu,s,o); ss+=__shfl_xor_sync(0xffffffffu,ss,o); }
    float mu=s*(1.f/128), var=ss*(1.f/128)-mu*mu, inv=rsqrtf(var+1e-5f);
    if(n<NN){
      #pragma unroll
      for(int i=0;i<4;i++){ int c=lane+32*i;
        float nv=(v[i]-mu)*inv*G[c]+BT[c];
        float f=d_feats[(size_t)n*128+c]+nv;
        d_feats[(size_t)n*128+c]=f;
        d_fcat[(size_t)n*FH+(size_t)(k+1)*128+c]=f; }
    }
  }
}

// ---------------- head MLP ----------------
__global__ void __launch_bounds__(256) k_fnn0(const float* __restrict__ W,const float* __restrict__ b){
  __shared__ float s_a[64*65];
  __shared__ float s_w[64*64];
  int tid=threadIdx.x;
  int jc0=blockIdx.x*64, n0=blockIdx.y*64;
  int r0=(tid>>4)*4, c0=(tid&15)*4;
  float acc[4][4];
  #pragma unroll
  for(int i=0;i<4;i++){acc[i][0]=0;acc[i][1]=0;acc[i][2]=0;acc[i][3]=0;}
  for(int ch=0;ch<12;ch++){
    __syncthreads();
    for(int i=tid;i<64*64;i+=256){int r=i>>6,c=i&63;int n=n0+r; s_a[r*65+c]= (n<NN)? siluf(d_fcat[(size_t)n*FH+ch*64+c]) : 0.f;}
    for(int i=tid;i<64*64;i+=256){int p=i>>6,c=i&63; s_w[i]=W[(size_t)(ch*64+p)*F2 + jc0+c];}
    __syncthreads();
    for(int p=0;p<64;p++){
      float4 w=*(float4*)(s_w+p*64+c0);
      #pragma unroll
      for(int i=0;i<4;i++){ float a=s_a[(r0+i)*65+p];
        acc[i][0]+=a*w.x; acc[i][1]+=a*w.y; acc[i][2]+=a*w.z; acc[i][3]+=a*w.w; }
    }
  }
  #pragma unroll
  for(int i=0;i<4;i++){int n=n0+r0+i; if(n<NN){
    #pragma unroll
    for(int j=0;j<4;j++) d_f1[(size_t)n*F2+jc0+c0+j]=siluf(acc[i][j]+__ldg(&b[jc0+c0+j]));
  }}
}

__global__ void __launch_bounds__(256) k_fnn(const float* __restrict__ W,const float* __restrict__ b,int which){
  __shared__ float s_a[64*65];
  __shared__ float s_w[64*64];
  const float* fin = which? d_f2 : d_f1;
  float* fout = which? d_f1 : d_f2;
  int tid=threadIdx.x;
  int jc0=blockIdx.x*64, n0=blockIdx.y*64;
  int r0=(tid>>4)*4, c0=(tid&15)*4;
  float acc[4][4];
  #pragma unroll
  for(int i=0;i<4;i++){acc[i][0]=0;acc[i][1]=0;acc[i][2]=0;acc[i][3]=0;}
  for(int ch=0;ch<4;ch++){
    __syncthreads();
    for(int i=tid;i<64*64;i+=256){int r=i>>6,c=i&63;int n=n0+r; s_a[r*65+c]= (n<NN)? fin[(size_t)n*F2+ch*64+c] : 0.f;}
    for(int i=tid;i<64*64;i+=256){int p=i>>6,c=i&63; s_w[i]=W[(size_t)(ch*64+p)*F2 + jc0+c];}
    __syncthreads();
    for(int p=0;p<64;p++){
      float4 w=*(float4*)(s_w+p*64+c0);
      #pragma unroll
      for(int i=0;i<4;i++){ float a=s_a[(r0+i)*65+p];
        acc[i][0]+=a*w.x; acc[i][1]+=a*w.y; acc[i][2]+=a*w.z; acc[i][3]+=a*w.w; }
    }
  }
  #pragma unroll
  for(int i=0;i<4;i++){int n=n0+r0+i; if(n<NN){
    #pragma unroll
    for(int j=0;j<4;j++) fout[(size_t)n*F2+jc0+c0+j]=siluf(acc[i][j]+__ldg(&b[jc0+c0+j]));
  }}
}

__global__ void k_pool(const int* __restrict__ batch){
  int n=blockIdx.x; int c=threadIdx.x;
  int b=batch[n];
  atomicAdd(&d_gsum[b*F2+c], d_f1[(size_t)n*F2+c]);
  if(c==0) atomicAdd(&d_gcnt[b],1.f);
}

__global__ void k_final(const float* __restrict__ gW0,const float* __restrict__ gb0,
                        const float* __restrict__ gW1,const float* __restrict__ gb1,
                        const float* __restrict__ gW2,const float* __restrict__ gb2,
                        float* __restrict__ out){
  __shared__ float s_g[256], s_h[256], s_red[8];
  int b=blockIdx.x, t=threadIdx.x;
  float cnt=fmaxf(d_gcnt[b],1.f);
  s_g[t]=d_gsum[b*F2+t]/cnt;
  __syncthreads();
  float a=gb0[t];
  #pragma unroll 8
  for(int p=0;p<256;p++) a+=s_g[p]*gW0[p*256+t];
  s_h[t]=siluf(a);
  __syncthreads();
  a=gb1[t];
  #pragma unroll 8
  for(int p=0;p<256;p++) a+=s_h[p]*gW1[p*256+t];
  float h=siluf(a);
  float v=h*gW2[t];
  #pragma unroll
  for(int o=16;o;o>>=1) v+=__shfl_xor_sync(0xffffffffu,v,o);
  if((t&31)==0) s_red[t>>5]=v;
  __syncthreads();
  if(t==0){ float tot=0.f;
    #pragma unroll
    for(int i=0;i<8;i++) tot+=s_red[i];
    out[b]=tot+gb2[0]; }
}

// ---------------- host ----------------
extern "C" void kernel_launch(void* const* d_in, const int* in_sizes, int n_in,
                              void* d_out, int out_size){
  const float* coords =(const float*)d_in[0];
  const int*   atomids=(const int*)d_in[1];
  const int*   eidx   =(const int*)d_in[2];
  const int*   batch  =(const int*)d_in[3];
  int s = (in_sizes[4]==11*DD) ? 4 : 5;   // skip num_graphs scalar if present
  const float* emb =(const float*)d_in[s+0];
  const float* keW1=(const float*)d_in[s+1];
  const float* keb1=(const float*)d_in[s+2];
  const float* keW2=(const float*)d_in[s+3];
  const float* keb2=(const float*)d_in[s+4];
  const float* keng=(const float*)d_in[s+5];
  const float* kenb=(const float*)d_in[s+6];
  const float* kn1g=(const float*)d_in[s+7];
  const float* kn1b=(const float*)d_in[s+8];
  const float* knW1=(const float*)d_in[s+9];
  const float* knb1=(const float*)d_in[s+10];
  const float* knW2=(const float*)d_in[s+11];
  const float* knb2=(const float*)d_in[s+12];
  const float* kn2g=(const float*)d_in[s+13];
  const float* kn2b=(const float*)d_in[s+14];
  const float* fW0 =(const float*)d_in[s+15];
  const float* fb0 =(const float*)d_in[s+16];
  const float* fW1 =(const float*)d_in[s+17];
  const float* fb1 =(const float*)d_in[s+18];
  const float* fW2 =(const float*)d_in[s+19];
  const float* fb2 =(const float*)d_in[s+20];
  const float* gW0 =(const float*)d_in[s+21];
  const float* gb0 =(const float*)d_in[s+22];
  const float* gW1 =(const float*)d_in[s+23];
  const float* gb1 =(const float*)d_in[s+24];
  const float* gW2 =(const float*)d_in[s+25];
  const float* gb2 =(const float*)d_in[s+26];
  float* out=(float*)d_out;

  const int FAB_SM  = (64*129 + 128*64)*4;                        // 65792
  const int EDGE_SM = (352*RS + 64 + 128 + 64 + 96 + 256)*4;      // 103808
  const int NODE_SM = (10304+16448+16384)*4;                      // 172544
  cudaFuncSetAttribute(k_fab,  cudaFuncAttributeMaxDynamicSharedMemorySize, FAB_SM);
  cudaFuncSetAttribute(k_edge, cudaFuncAttributeMaxDynamicSharedMemorySize, EDGE_SM);
  cudaFuncSetAttribute(k_node, cudaFuncAttributeMaxDynamicSharedMemorySize, NODE_SM);

  k_zero_init<<<65,256>>>();
  k_feats<<<NN,128>>>(emb,atomids);
  k_deg<<<EE/256,256>>>(eidx);
  k_ea<<<EE/256,256>>>(coords,eidx);
  k_wprep<<<1320,256>>>(keW1,keW2);   // 5*11*(64+32)*64 = 337920 elems
  for(int k=0;k<KK;k++){
    k_zero_msum<<<(NN*MM)/256,256>>>();
    k_fab<<<dim3(11,157,2),256,FAB_SM>>>(keW1,k);
    k_edge<<<EE/128,256,EDGE_SM>>>(eidx,keW1,keb1,keb2,keng,kenb,k);
    k_xcat<<<NN/8,256>>>(keng,kenb,kn1g,kn1b,k);
    k_node<<<157,256,NODE_SM>>>(knW1,knb1,knW2,knb2,kn2g,kn2b,k);
  }
  k_fnn0<<<dim3(4,157),256>>>(fW0,fb0);
  k_fnn<<<dim3(4,157),256>>>(fW1,fb1,0);
  k_fnn<<<dim3(4,157),256>>>(fW2,fb2,1);
  k_pool<<<NN,256>>>(batch);
  k_final<<<BB,256>>>(gW0,gb0,gW1,gb1,gW2,gb2,out);
}

// round 8
// speedup vs baseline: 2.1051x; 1.1764x over previous
#include <cuda_runtime.h>
#include <math.h>

#define NN 10000
#define EE 160000
#define BB 64
#define DD 128
#define MM 32
#define EINN 321
#define H1 642
#define KK 5
#define FH 768
#define F2 256
#define FASTRIDE 644

// permuted column index: fragment pair (k, k+4) contiguous
#define PERM(k) (((k)&3)*18 + ((k)>>2))
#define RS 72   // row stride (mod 32 == 8 -> conflict-free with qc*18)

// ---------------- scratch (zero-initialized device globals) ----------------
__device__ float d_feats[NN*DD];
__device__ float d_eap[EE*RS];          // permuted tf32 edge attrs (sin/cos only)
__device__ float d_dcol[EE];            // fp32 squared distance per edge
__device__ float d_deg[NN];
__device__ float d_FA[NN*FASTRIDE + 256];
__device__ float d_FB[NN*FASTRIDE + 256];
__device__ float d_msum[NN*MM];
__device__ float d_xcat[NN*160];
__device__ float d_fcat[NN*FH];
__device__ float d_f1[NN*F2];
__device__ float d_f2[NN*F2];
__device__ float d_gsum[BB*F2];
__device__ float d_gcnt[BB];
__device__ float d_w1p[KK*11*64*RS];    // pre-permuted edge W1 chunks
__device__ float d_w2p[KK*11*32*RS];    // pre-permuted edge W2 chunks
__device__ float d_wfabp[KK*2*11*2*64*RS]; // pre-permuted FA/FB weights
__device__ float d_wf0p[4*12*64*RS];    // pre-permuted fW0
__device__ float d_wf1p[4*4*64*RS];     // pre-permuted fW1
__device__ float d_wf2p[4*4*64*RS];     // pre-permuted fW2

__device__ __forceinline__ float siluf(float x){
  return __fdividef(x, 1.f+__expf(-x));
}

__device__ __forceinline__ float tf32r(float x){
  float r; asm("cvt.rna.tf32.f32 %0,%1;" : "=f"(r) : "f"(x)); return r;
}
__device__ __forceinline__ void mma8(float4 &c, unsigned a0,unsigned a1,unsigned a2,unsigned a3,
                                     unsigned b0,unsigned b1){
  asm("mma.sync.aligned.m16n8k8.row.col.f32.tf32.tf32.f32 "
      "{%0,%1,%2,%3},{%4,%5,%6,%7},{%8,%9},{%0,%1,%2,%3};"
      : "+f"(c.x),"+f"(c.y),"+f"(c.z),"+f"(c.w)
      : "r"(a0),"r"(a1),"r"(a2),"r"(a3),"r"(b0),"r"(b1));
}

// ---------------- init / zero kernels ----------------
__global__ void k_zero_init(){
  int i = blockIdx.x*256+threadIdx.x;
  if(i<NN) d_deg[i]=0.f;
  if(i<BB*F2) d_gsum[i]=0.f;
  if(i<BB) d_gcnt[i]=0.f;
}
__global__ void k_zero_msum(){
  int i = blockIdx.x*256+threadIdx.x;
  d_msum[i]=0.f;
}
__global__ void k_feats(const float* __restrict__ emb, const int* __restrict__ atomids){
  int n=blockIdx.x; int c=threadIdx.x;
  float v=emb[atomids[n]*DD+c];
  d_feats[n*DD+c]=v;
  d_fcat[(size_t)n*FH+c]=v;
}
__global__ void k_deg(const int* __restrict__ eidx){
  int e=blockIdx.x*256+threadIdx.x;
  atomicAdd(&d_deg[eidx[EE+e]],1.f);
}
__global__ void k_ea(const float* __restrict__ coords, const int* __restrict__ eidx){
  int e=blockIdx.x*256+threadIdx.x;
  int s=eidx[e], t2=eidx[EE+e];
  float dx=coords[3*s]-coords[3*t2];
  float dy=coords[3*s+1]-coords[3*t2+1];
  float dz=coords[3*s+2]-coords[3*t2+2];
  float d=dx*dx+dy*dy+dz*dz;
  float* o=&d_eap[(size_t)e*RS];
  float x=d;
  #pragma unroll
  for(int i=0;i<32;i++){
    float sv,cv; __sincosf(x,&sv,&cv);
    o[PERM(i)]=tf32r(sv); o[PERM(32+i)]=tf32r(cv);
    x*=0.5f;
  }
  d_dcol[e]=d;
}

// ---------------- one-shot weight permutes ----------------
__global__ void k_wprep(const float* __restrict__ keW1, const float* __restrict__ keW2){
  int i = blockIdx.x*256+threadIdx.x;
  const int W1TOT = KK*11*64*64;
  const int W2TOT = KK*11*32*64;
  if(i < W1TOT){
    int kk=i&63; int n=(i>>6)&63; int ch=(i>>12)%11; int k=i/(64*64*11);
    int j=ch*64+n;
    float v = (j<H1)? tf32r(keW1[(size_t)k*EINN*H1 + (size_t)(256+kk)*H1 + j]) : 0.f;
    d_w1p[(size_t)(((k*11+ch)*64)+n)*RS + PERM(kk)] = v;
  } else if(i < W1TOT+W2TOT){
    int m=i-W1TOT;
    int kk=m&63; int n=(m>>6)&31; int ch=(m>>11)%11; int k=m/(32*64*11);
    int j=ch*64+kk;
    float v = (j<H1)? tf32r(keW2[(size_t)k*H1*MM + (size_t)j*MM + n]) : 0.f;
    d_w2p[(size_t)(((k*11+ch)*32)+n)*RS + PERM(kk)] = v;
  }
}

// FA/FB weights: keW1[k][part*128 + kc*64 + kk][ch*64+n]
__global__ void k_wprep_fab(const float* __restrict__ keW1){
  int i = blockIdx.x*256+threadIdx.x;   // total KK*2*11*2*64*64 = 901120
  int kk=i&63; int i2=i>>6;
  int n=i2&63; i2>>=6;
  int kc=i2&1; i2>>=1;
  int ch=i2%11; i2/=11;
  int part=i2&1; int k=i2>>1;
  int p = part*128 + kc*64 + kk;
  int j = ch*64 + n;
  float v = (j<H1)? tf32r(keW1[(size_t)k*EINN*H1 + (size_t)p*H1 + j]) : 0.f;
  d_wfabp[(size_t)((((k*2+part)*11+ch)*2+kc)*64 + n)*RS + PERM(kk)] = v;
}

// head weights: fW0 [768x256] (cc 4, kc 12), fW1/fW2 [256x256] (cc 4, kc 4)
__global__ void k_wprep_fnn(const float* __restrict__ fW0,
                            const float* __restrict__ fW1,
                            const float* __restrict__ fW2){
  int i = blockIdx.x*256+threadIdx.x;   // total 196608 + 65536 + 65536 = 327680
  if(i < 196608){
    int kk=i&63; int n=(i>>6)&63; int r=i>>12;   // 0..47
    int kc=r%12, cc=r/12;
    d_wf0p[(size_t)((cc*12+kc)*64+n)*RS + PERM(kk)] =
      tf32r(fW0[(size_t)(kc*64+kk)*F2 + cc*64+n]);
  } else if(i < 262144){
    int j=i-196608;
    int kk=j&63; int n=(j>>6)&63; int r=j>>12;   // 0..15
    int kc=r&3, cc=r>>2;
    d_wf1p[(size_t)((cc*4+kc)*64+n)*RS + PERM(kk)] =
      tf32r(fW1[(size_t)(kc*64+kk)*F2 + cc*64+n]);
  } else {
    int j=i-262144;
    int kk=j&63; int n=(j>>6)&63; int r=j>>12;
    int kc=r&3, cc=r>>2;
    d_wf2p[(size_t)((cc*4+kc)*64+n)*RS + PERM(kk)] =
      tf32r(fW2[(size_t)(kc*64+kk)*F2 + cc*64+n]);
  }
}

// ---------------- per-layer: FA/FB = feats @ W1[part] via tf32 MMA ----------------
// grid (11, 79, 2), 256 thr; block = 128 nodes x 64 cols, K=128 (2 chunks)
__global__ void __launch_bounds__(256,2) k_fab_mma(int k){
  extern __shared__ float sm[];
  float* s_f = sm;              // 2 planes of 128*72
  float* s_b = sm + 2*128*RS;   // 2 tiles of 64*72
  int tid=threadIdx.x;
  int ch=blockIdx.x, nb=blockIdx.y, part=blockIdx.z;
  int n0 = nb*128;
  // stage A (feats, permuted tf32)
  #pragma unroll
  for(int t=0;t<16;t++){
    int lin = tid + t*256;            // float4 index over [128][32]
    int r = lin>>5, c4 = (lin&31)*4;
    int n = n0 + r;
    float4 v = (n<NN)? *(const float4*)(d_feats + (size_t)n*DD + c4) : make_float4(0,0,0,0);
    int kc = c4>>6, cc = c4&63;
    float* dst = s_f + kc*(128*RS) + r*RS + (cc>>2);
    dst[0]=tf32r(v.x); dst[18]=tf32r(v.y); dst[36]=tf32r(v.z); dst[54]=tf32r(v.w);
  }
  // stage B (both K-chunks contiguous)
  {
    const float4* src = (const float4*)(d_wfabp + (size_t)(((k*2+part)*11+ch)*2)*(64*RS));
    float4* dst = (float4*)s_b;
    #pragma unroll
    for(int t=0;t<9;t++){ int i=tid+t*256; if(i<2304) dst[i]=src[i]; }
  }
  __syncthreads();
  int w=tid>>5, l=tid&31, qr=l>>2, qc=l&3;
  int ra=w*16+qr, rb=ra+8, aoff=qc*18;
  float4 c1[8];
  #pragma unroll
  for(int t=0;t<8;t++) c1[t]=make_float4(0,0,0,0);
  #pragma unroll
  for(int kc=0;kc<2;kc++){
    float* sa = s_f + kc*(128*RS);
    float* sb = s_b + kc*(64*RS);
    #pragma unroll
    for(int ks=0;ks<8;ks++){
      float2 A0=*(float2*)(sa+ra*RS+aoff+2*ks);
      float2 A1=*(float2*)(sa+rb*RS+aoff+2*ks);
      unsigned a0=__float_as_uint(A0.x), a2=__float_as_uint(A0.y);
      unsigned a1=__float_as_uint(A1.x), a3=__float_as_uint(A1.y);
      #pragma unroll
      for(int nt=0;nt<8;nt++){
        float2 Bv=*(float2*)(sb+(nt*8+qr)*RS+aoff+2*ks);
        mma8(c1[nt],a0,a1,a2,a3,__float_as_uint(Bv.x),__float_as_uint(Bv.y));
      }
    }
  }
  float* OUT = part? d_FB : d_FA;
  int na=n0+ra, nb2=n0+rb;
  #pragma unroll
  for(int nt=0;nt<8;nt++){
    int col = ch*64 + nt*8 + 2*qc;
    if(col<643){
      if(na<NN)  *(float2*)(OUT+(size_t)na*FASTRIDE+col)=make_float2(c1[nt].x,c1[nt].y);
      if(nb2<NN) *(float2*)(OUT+(size_t)nb2*FASTRIDE+col)=make_float2(c1[nt].z,c1[nt].w);
    }
  }
}

// ---------------- head MLP via tf32 MMA ----------------
// grid (2, 79), 256 thr; block = 128 nodes x 128 cols
// stage 0: silu(d_fcat) @ fW0 -> d_f1 (KC=12); stage 1: d_f1 @ fW1 -> d_f2; stage 2: d_f2 @ fW2 -> d_f1
__global__ void __launch_bounds__(256,2) k_fnn_mma(const float* __restrict__ bias, int stage){
  const float* Wp = (stage==0)? d_wf0p : ((stage==1)? d_wf1p : d_wf2p);
  const float* in = (stage==0)? d_fcat : ((stage==1)? d_f1 : d_f2);
  float* out      = (stage==1)? d_f2 : d_f1;
  int KC          = (stage==0)? 12 : 4;
  int dosilu      = (stage==0);
  extern __shared__ float sm[];
  float* s_a = sm;              // 128*72
  float* s_b = sm + 128*RS;     // 2 tiles of 64*72
  int tid=threadIdx.x;
  int n0 = blockIdx.y*128;
  int cc0 = blockIdx.x*2;
  int w=tid>>5, l=tid&31, qr=l>>2, qc=l&3;
  int ra=w*16+qr, rb=ra+8, aoff=qc*18;
  int INST = KC*64;
  float4 c1[16];
  #pragma unroll
  for(int t=0;t<16;t++) c1[t]=make_float4(0,0,0,0);
  for(int kc=0;kc<KC;kc++){
    __syncthreads();
    // stage A chunk
    #pragma unroll
    for(int t=0;t<8;t++){
      int lin=tid+t*256;             // float4 over [128][16]
      int r=lin>>4, c4=(lin&15)*4;
      int n=n0+r;
      float4 v = (n<NN)? *(const float4*)(in + (size_t)n*INST + kc*64 + c4) : make_float4(0,0,0,0);
      if(dosilu){ v.x=siluf(v.x); v.y=siluf(v.y); v.z=siluf(v.z); v.w=siluf(v.w); }
      float* dst = s_a + r*RS + (c4>>2);
      dst[0]=tf32r(v.x); dst[18]=tf32r(v.y); dst[36]=tf32r(v.z); dst[54]=tf32r(v.w);
    }
    // stage B (two 64-col tiles)
    {
      const float4* s0=(const float4*)(Wp + (size_t)(cc0*KC+kc)*(64*RS));
      const float4* s1=(const float4*)(Wp + (size_t)((cc0+1)*KC+kc)*(64*RS));
      float4* d0=(float4*)s_b;
      float4* d1=(float4*)(s_b+64*RS);
      #pragma unroll
      for(int t=0;t<5;t++){ int i=tid+t*256; if(i<1152){ d0[i]=s0[i]; d1[i]=s1[i]; } }
    }
    __syncthreads();
    #pragma unroll
    for(int ks=0;ks<8;ks++){
      float2 A0=*(float2*)(s_a+ra*RS+aoff+2*ks);
      float2 A1=*(float2*)(s_a+rb*RS+aoff+2*ks);
      unsigned a0=__float_as_uint(A0.x), a2=__float_as_uint(A0.y);
      unsigned a1=__float_as_uint(A1.x), a3=__float_as_uint(A1.y);
      #pragma unroll
      for(int nt=0;nt<16;nt++){
        float* sb = s_b + (nt>>3)*(64*RS);
        float2 Bv=*(float2*)(sb+((nt&7)*8+qr)*RS+aoff+2*ks);
        mma8(c1[nt],a0,a1,a2,a3,__float_as_uint(Bv.x),__float_as_uint(Bv.y));
      }
    }
  }
  int na=n0+ra, nb2=n0+rb;
  #pragma unroll
  for(int nt=0;nt<16;nt++){
    int col = cc0*64 + nt*8 + 2*qc;
    float b0=__ldg(&bias[col]), b1=__ldg(&bias[col+1]);
    if(na<NN)  *(float2*)(out+(size_t)na*F2+col)=make_float2(siluf(c1[nt].x+b0),siluf(c1[nt].y+b1));
    if(nb2<NN) *(float2*)(out+(size_t)nb2*F2+col)=make_float2(siluf(c1[nt].z+b0),siluf(c1[nt].w+b1));
  }
}

// ---------------- per-layer: fused edge MLP via tf32 MMA + LN + scatter ----------------
// grid 1250, 256 thr (8 warps); block = 128 edges
__global__ void __launch_bounds__(256,2) k_edge(const int* __restrict__ eidx,
   const float* __restrict__ keW1,const float* __restrict__ keb1,
   const float* __restrict__ keb2,
   const float* __restrict__ keng,const float* __restrict__ kenb,int k){
  extern __shared__ float sm[];
  float* s_ea = sm;                    // 128*RS
  float* s_w1 = s_ea + 128*RS;         // 64*RS
  float* s_h  = s_w1 + 64*RS;          // 128*RS
  float* s_w2 = s_h  + 128*RS;         // 32*RS
  float* s_w1d= s_w2 + 32*RS;          // 64  (d-row of W1 chunk)
  float* s_d  = s_w1d + 64;            // 128 (d per edge)
  float* s_b1 = s_d + 128;             // 64
  float* s_b2 = s_b1 + 64;             // 32
  float* s_g  = s_b2 + 32;             // 32
  float* s_bt = s_g + 32;              // 32
  int* s_dst = (int*)(s_bt+32);        // 128
  int* s_src = s_dst + 128;            // 128
  int tid=threadIdx.x;
  int e0=blockIdx.x*128;
  {
    const float4* src=(const float4*)(d_eap + (size_t)e0*RS);
    float4* dst=(float4*)s_ea;
    #pragma unroll
    for(int i=0;i<9;i++) dst[tid+256*i]=src[tid+256*i];
  }
  if(tid<128){ s_dst[tid]=eidx[EE+e0+tid]; s_src[tid]=eidx[e0+tid];
               s_d[tid]=d_dcol[e0+tid]; }
  if(tid>=128 && tid<160){ int c=tid-128; s_b2[c]=keb2[k*MM+c]; s_g[c]=keng[k*MM+c]; s_bt[c]=kenb[k*MM+c]; }
  const float* W1c = keW1 + (size_t)k*EINN*H1 + (size_t)256*H1;
  const float* B1  = keb1 + (size_t)k*H1;

  int w=tid>>5, l=tid&31, qr=l>>2, qc=l&3;
  int ra=w*16+qr, rb=ra+8;
  int aoff=qc*18;

  float4 c2[4];
  #pragma unroll
  for(int t=0;t<4;t++) c2[t]=make_float4(0.f,0.f,0.f,0.f);

  for(int ch=0; ch<11; ch++){
    int jc0=ch*64;
    __syncthreads();
    {
      const float4* w1src=(const float4*)(d_w1p + (size_t)((k*11+ch)*64)*RS);
      float4* w1dst=(float4*)s_w1;
      #pragma unroll
      for(int i=0;i<4;i++) w1dst[tid+256*i]=w1src[tid+256*i];
      if(tid<128) w1dst[tid+1024]=w1src[tid+1024];
      const float4* w2src=(const float4*)(d_w2p + (size_t)((k*11+ch)*32)*RS);
      float4* w2dst=(float4*)s_w2;
      #pragma unroll
      for(int i=0;i<2;i++) w2dst[tid+256*i]=w2src[tid+256*i];
      if(tid<64) w2dst[tid+512]=w2src[tid+512];
      if(tid<64){ int j=jc0+tid; s_b1[tid]=(j<H1)?B1[j]:0.f;
                  s_w1d[tid]=(j<H1)? W1c[(size_t)64*H1+j] : 0.f; }
    }
    __syncthreads();

    float4 c1[8];
    #pragma unroll
    for(int t=0;t<8;t++) c1[t]=make_float4(0.f,0.f,0.f,0.f);
    #pragma unroll
    for(int ks=0;ks<8;ks++){
      float2 A0=*(float2*)(s_ea+ra*RS+aoff+2*ks);
      float2 A1=*(float2*)(s_ea+rb*RS+aoff+2*ks);
      unsigned a0=__float_as_uint(A0.x), a2=__float_as_uint(A0.y);
      unsigned a1=__float_as_uint(A1.x), a3=__float_as_uint(A1.y);
      #pragma unroll
      for(int nt=0;nt<8;nt++){
        float2 Bv=*(float2*)(s_w1+(nt*8+qr)*RS+aoff+2*ks);
        mma8(c1[nt],a0,a1,a2,a3,__float_as_uint(Bv.x),__float_as_uint(Bv.y));
      }
    }
    {
      int nda=s_dst[ra], nsa=s_src[ra], ndb=s_dst[rb], nsb=s_src[rb];
      float da=s_d[ra], db=s_d[rb];
      const float* FAa=d_FA+(size_t)nda*FASTRIDE+jc0;
      const float* FBa=d_FB+(size_t)nsa*FASTRIDE+jc0;
      const float* FAb=d_FA+(size_t)ndb*FASTRIDE+jc0;
      const float* FBb=d_FB+(size_t)nsb*FASTRIDE+jc0;
      #pragma unroll
      for(int nt=0;nt<8;nt++){
        int col0=nt*8+2*qc;
        float2 faa=*(const float2*)(FAa+col0);
        float2 fba=*(const float2*)(FBa+col0);
        float2 fab=*(const float2*)(FAb+col0);
        float2 fbb=*(const float2*)(FBb+col0);
        float b0=s_b1[col0], b1f=s_b1[col0+1];
        float w0=s_w1d[col0], w1v=s_w1d[col0+1];
        int p0=((col0&3)*18) + (col0>>2);
        s_h[ra*RS+p0]   =tf32r(siluf(c1[nt].x+b0 +da*w0 +faa.x+fba.x));
        s_h[ra*RS+p0+18]=tf32r(siluf(c1[nt].y+b1f+da*w1v+faa.y+fba.y));
        s_h[rb*RS+p0]   =tf32r(siluf(c1[nt].z+b0 +db*w0 +fab.x+fbb.x));
        s_h[rb*RS+p0+18]=tf32r(siluf(c1[nt].w+b1f+db*w1v+fab.y+fbb.y));
      }
    }
    __syncthreads();
    #pragma unroll
    for(int ks=0;ks<8;ks++){
      float2 A0=*(float2*)(s_h+ra*RS+aoff+2*ks);
      float2 A1=*(float2*)(s_h+rb*RS+aoff+2*ks);
      unsigned a0=__float_as_uint(A0.x), a2=__float_as_uint(A0.y);
      unsigned a1=__float_as_uint(A1.x), a3=__float_as_uint(A1.y);
      #pragma unroll
      for(int nt=0;nt<4;nt++){
        float2 Bv=*(float2*)(s_w2+(nt*8+qr)*RS+aoff+2*ks);
        mma8(c2[nt],a0,a1,a2,a3,__float_as_uint(Bv.x),__float_as_uint(Bv.y));
      }
    }
  }
  float va[8], vb[8];
  #pragma unroll
  for(int nt=0;nt<4;nt++){
    int col0=nt*8+2*qc;
    va[2*nt]  =siluf(c2[nt].x+s_b2[col0]);
    va[2*nt+1]=siluf(c2[nt].y+s_b2[col0+1]);
    vb[2*nt]  =siluf(c2[nt].z+s_b2[col0]);
    vb[2*nt+1]=siluf(c2[nt].w+s_b2[col0+1]);
  }
  float sa=0.f,ssa=0.f,sb=0.f,ssb=0.f;
  #pragma unroll
  for(int i=0;i<8;i++){ sa+=va[i]; ssa+=va[i]*va[i]; sb+=vb[i]; ssb+=vb[i]*vb[i]; }
  #pragma unroll
  for(int o=1;o<4;o<<=1){
    sa+=__shfl_xor_sync(0xffffffffu,sa,o); ssa+=__shfl_xor_sync(0xffffffffu,ssa,o);
    sb+=__shfl_xor_sync(0xffffffffu,sb,o); ssb+=__shfl_xor_sync(0xffffffffu,ssb,o);
  }
  float mua=sa*(1.f/MM), vara=ssa*(1.f/MM)-mua*mua, inva=rsqrtf(vara+1e-5f);
  float mub=sb*(1.f/MM), varb=ssb*(1.f/MM)-mub*mub, invb=rsqrtf(varb+1e-5f);
  float* pa=&d_msum[(size_t)s_dst[ra]*MM];
  float* pb=&d_msum[(size_t)s_dst[rb]*MM];
  #pragma unroll
  for(int nt=0;nt<4;nt++){
    int col0=nt*8+2*qc;
    atomicAdd(pa+col0,  (va[2*nt]  -mua)*inva*s_g[col0]  +s_bt[col0]);
    atomicAdd(pa+col0+1,(va[2*nt+1]-mua)*inva*s_g[col0+1]+s_bt[col0+1]);
    atomicAdd(pb+col0,  (vb[2*nt]  -mub)*invb*s_g[col0]  +s_bt[col0]);
    atomicAdd(pb+col0+1,(vb[2*nt+1]-mub)*invb*s_g[col0+1]+s_bt[col0+1]);
  }
}

// ---------------- per-layer: xcat = [LN(feats) | LN(msum/deg)] ----------------
__global__ void k_xcat(const float* __restrict__ keng,const float* __restrict__ kenb,
                       const float* __restrict__ kn1g,const float* __restrict__ kn1b,int k){
  int warp=threadIdx.x>>5, lane=threadIdx.x&31;
  int n=blockIdx.x*8+warp;
  const float* g1=kn1g+(size_t)k*128; const float* b1=kn1b+(size_t)k*128;
  float v[4],s=0.f,ss=0.f;
  #pragma unroll
  for(int i=0;i<4;i++){ float x=d_feats[(size_t)n*128+lane+32*i]; v[i]=x; s+=x; ss+=x*x; }
  #pragma unroll
  for(int o=16;o;o>>=1){ s+=__shfl_xor_sync(0xffffffffu,s,o); ss+=__shfl_xor_sync(0xffffffffu,ss,o); }
  float mu=s*(1.f/128), var=ss*(1.f/128)-mu*mu, inv=rsqrtf(var+1e-5f);
  #pragma unroll
  for(int i=0;i<4;i++){ int c=lane+32*i; d_xcat[(size_t)n*160+c]=(v[i]-mu)*inv*g1[c]+b1[c]; }
  float m=d_msum[(size_t)n*MM+lane]/fmaxf(d_deg[n],1.f);
  float s2=m, ss2=m*m;
  #pragma unroll
  for(int o=16;o;o>>=1){ s2+=__shfl_xor_sync(0xffffffffu,s2,o); ss2+=__shfl_xor_sync(0xffffffffu,ss2,o); }
  float mu2=s2*(1.f/MM), var2=ss2*(1.f/MM)-mu2*mu2, inv2=rsqrtf(var2+1e-5f);
  d_xcat[(size_t)n*160+128+lane]=(m-mu2)*inv2*keng[k*MM+lane]+kenb[k*MM+lane];
}

// ---------------- per-layer: fused node MLP + LN + residual (fp32 scalar) ----------------
__global__ void __launch_bounds__(256) k_node(const float* __restrict__ knW1,const float* __restrict__ knb1,
    const float* __restrict__ knW2,const float* __restrict__ knb2,
    const float* __restrict__ kn2g,const float* __restrict__ kn2b,int k){
  extern __shared__ float sm[];
  float* s_x=sm;            // 64*161=10304
  float* s_h=s_x+10304;     // 64*257=16448
  float* s_w=s_h+16448;     // 256*64=16384
  int tid=threadIdx.x;
  int n0=blockIdx.x*64;
  const float* W1=knW1+(size_t)k*160*256;
  const float* B1=knb1+(size_t)k*256;
  const float* W2=knW2+(size_t)k*256*128;
  const float* B2=knb2+(size_t)k*128;
  const float* G =kn2g+(size_t)k*128;
  const float* BT=kn2b+(size_t)k*128;
  for(int i=tid;i<64*160;i+=256){int r=i/160,c=i-r*160;int n=n0+r; s_x[r*161+c]= (n<NN)? d_xcat[(size_t)n*160+c]:0.f;}
  int r0=(tid>>4)*4, c0=(tid&15)*4;
  for(int oc=0;oc<4;oc++){
    __syncthreads();
    for(int i=tid;i<160*64;i+=256){int p=i>>6,c=i&63; s_w[i]=W1[(size_t)p*256+oc*64+c];}
    __syncthreads();
    float a4[4][4];
    #pragma unroll
    for(int i=0;i<4;i++){a4[i][0]=0;a4[i][1]=0;a4[i][2]=0;a4[i][3]=0;}
    for(int p=0;p<160;p++){
      float4 w=*(float4*)(s_w+p*64+c0);
      #pragma unroll
      for(int i=0;i<4;i++){ float a=s_x[(r0+i)*161+p];
        a4[i][0]+=a*w.x; a4[i][1]+=a*w.y; a4[i][2]+=a*w.z; a4[i][3]+=a*w.w; }
    }
    #pragma unroll
    for(int i=0;i<4;i++){
      #pragma unroll
      for(int j=0;j<4;j++){ int col=oc*64+c0+j;
        s_h[(r0+i)*257+col]=siluf(a4[i][j]+__ldg(&B1[col])); }
    }
  }
  __syncthreads();
  for(int oc=0;oc<2;oc++){
    if(oc) __syncthreads();
    for(int i=tid;i<256*64;i+=256){int p=i>>6,c=i&63; s_w[i]=W2[(size_t)p*128+oc*64+c];}
    __syncthreads();
    float a4[4][4];
    #pragma unroll
    for(int i=0;i<4;i++){a4[i][0]=0;a4[i][1]=0;a4[i][2]=0;a4[i][3]=0;}
    for(int p=0;p<256;p++){
      float4 w=*(float4*)(s_w+p*64+c0);
      #pragma unroll
      for(int i=0;i<4;i++){ float a=s_h[(r0+i)*257+p];
        a4[i][0]+=a*w.x; a4[i][1]+=a*w.y; a4[i][2]+=a*w.z; a4[i][3]+=a*w.w; }
    }
    #pragma unroll
    for(int i=0;i<4;i++){
      #pragma unroll
      for(int j=0;j<4;j++){ int col=oc*64+c0+j;
        s_x[(r0+i)*129+col]=a4[i][j]+__ldg(&B2[col]); }
    }
  }
  __syncthreads();
  int w=tid>>5, lane=tid&31;
  for(int rr=w; rr<64; rr+=8){
    int n=n0+rr;
    float v[4],s=0.f,ss=0.f;
    #pragma unroll
    for(int i=0;i<4;i++){ float x=s_x[rr*129+lane+32*i]; v[i]=x; s+=x; ss+=x*x; }
    #pragma unroll
    for(int o=16;o;o>>=1){ s+=__shfl_xor_sync(0xffffffffu,s,o); ss+=__shfl_xor_sync(0xffffffffu,ss,o); }
    float mu=s*(1.f/128), var=ss*(1.f/128)-mu*mu, inv=rsqrtf(var+1e-5f);
    if(n<NN){
      #pragma unroll
      for(int i=0;i<4;i++){ int c=lane+32*i;
        float nv=(v[i]-mu)*inv*G[c]+BT[c];
        float f=d_feats[(size_t)n*128+c]+nv;
        d_feats[(size_t)n*128+c]=f;
        d_fcat[(size_t)n*FH+(size_t)(k+1)*128+c]=f; }
    }
  }
}

__global__ void k_pool(const int* __restrict__ batch){
  int n=blockIdx.x; int c=threadIdx.x;
  int b=batch[n];
  atomicAdd(&d_gsum[b*F2+c], d_f1[(size_t)n*F2+c]);
  if(c==0) atomicAdd(&d_gcnt[b],1.f);
}

__global__ void k_final(const float* __restrict__ gW0,const float* __restrict__ gb0,
                        const float* __restrict__ gW1,const float* __restrict__ gb1,
                        const float* __restrict__ gW2,const float* __restrict__ gb2,
                        float* __restrict__ out){
  __shared__ float s_g[256], s_h[256], s_red[8];
  int b=blockIdx.x, t=threadIdx.x;
  float cnt=fmaxf(d_gcnt[b],1.f);
  s_g[t]=d_gsum[b*F2+t]/cnt;
  __syncthreads();
  float a=gb0[t];
  #pragma unroll 8
  for(int p=0;p<256;p++) a+=s_g[p]*gW0[p*256+t];
  s_h[t]=siluf(a);
  __syncthreads();
  a=gb1[t];
  #pragma unroll 8
  for(int p=0;p<256;p++) a+=s_h[p]*gW1[p*256+t];
  float h=siluf(a);
  float v=h*gW2[t];
  #pragma unroll
  for(int o=16;o;o>>=1) v+=__shfl_xor_sync(0xffffffffu,v,o);
  if((t&31)==0) s_red[t>>5]=v;
  __syncthreads();
  if(t==0){ float tot=0.f;
    #pragma unroll
    for(int i=0;i<8;i++) tot+=s_red[i];
    out[b]=tot+gb2[0]; }
}

// ---------------- host ----------------
extern "C" void kernel_launch(void* const* d_in, const int* in_sizes, int n_in,
                              void* d_out, int out_size){
  const float* coords =(const float*)d_in[0];
  const int*   atomids=(const int*)d_in[1];
  const int*   eidx   =(const int*)d_in[2];
  const int*   batch  =(const int*)d_in[3];
  int s = (in_sizes[4]==11*DD) ? 4 : 5;   // skip num_graphs scalar if present
  const float* emb =(const float*)d_in[s+0];
  const float* keW1=(const float*)d_in[s+1];
  const float* keb1=(const float*)d_in[s+2];
  const float* keW2=(const float*)d_in[s+3];
  const float* keb2=(const float*)d_in[s+4];
  const float* keng=(const float*)d_in[s+5];
  const float* kenb=(const float*)d_in[s+6];
  const float* kn1g=(const float*)d_in[s+7];
  const float* kn1b=(const float*)d_in[s+8];
  const float* knW1=(const float*)d_in[s+9];
  const float* knb1=(const float*)d_in[s+10];
  const float* knW2=(const float*)d_in[s+11];
  const float* knb2=(const float*)d_in[s+12];
  const float* kn2g=(const float*)d_in[s+13];
  const float* kn2b=(const float*)d_in[s+14];
  const float* fW0 =(const float*)d_in[s+15];
  const float* fb0 =(const float*)d_in[s+16];
  const float* fW1 =(const float*)d_in[s+17];
  const float* fb1 =(const float*)d_in[s+18];
  const float* fW2 =(const float*)d_in[s+19];
  const float* fb2 =(const float*)d_in[s+20];
  const float* gW0 =(const float*)d_in[s+21];
  const float* gb0 =(const float*)d_in[s+22];
  const float* gW1 =(const float*)d_in[s+23];
  const float* gb1 =(const float*)d_in[s+24];
  const float* gW2 =(const float*)d_in[s+25];
  const float* gb2 =(const float*)d_in[s+26];
  float* out=(float*)d_out;

  const int EDGE_SM = (352*RS + 64 + 128 + 64 + 96 + 256)*4;      // 103808
  const int NODE_SM = (10304+16448+16384)*4;                      // 172544
  const int FAB_SM  = (2*128*RS + 2*64*RS)*4;                     // 110592
  const int FNN_SM  = (128*RS + 2*64*RS)*4;                       // 73728
  cudaFuncSetAttribute(k_edge,    cudaFuncAttributeMaxDynamicSharedMemorySize, EDGE_SM);
  cudaFuncSetAttribute(k_node,    cudaFuncAttributeMaxDynamicSharedMemorySize, NODE_SM);
  cudaFuncSetAttribute(k_fab_mma, cudaFuncAttributeMaxDynamicSharedMemorySize, FAB_SM);
  cudaFuncSetAttribute(k_fnn_mma, cudaFuncAttributeMaxDynamicSharedMemorySize, FNN_SM);

  k_zero_init<<<65,256>>>();
  k_feats<<<NN,128>>>(emb,atomids);
  k_deg<<<EE/256,256>>>(eidx);
  k_ea<<<EE/256,256>>>(coords,eidx);
  k_wprep<<<1320,256>>>(keW1,keW2);
  k_wprep_fab<<<3520,256>>>(keW1);      // 901120 elems
  k_wprep_fnn<<<1280,256>>>(fW0,fW1,fW2); // 327680 elems
  for(int k=0;k<KK;k++){
    k_zero_msum<<<(NN*MM)/256,256>>>();
    k_fab_mma<<<dim3(11,79,2),256,FAB_SM>>>(k);
    k_edge<<<EE/128,256,EDGE_SM>>>(eidx,keW1,keb1,keb2,keng,kenb,k);
    k_xcat<<<NN/8,256>>>(keng,kenb,kn1g,kn1b,k);
    k_node<<<157,256,NODE_SM>>>(knW1,knb1,knW2,knb2,kn2g,kn2b,k);
  }
  k_fnn_mma<<<dim3(2,79),256,FNN_SM>>>(fb0, 0);
  k_fnn_mma<<<dim3(2,79),256,FNN_SM>>>(fb1, 1);
  k_fnn_mma<<<dim3(2,79),256,FNN_SM>>>(fb2, 2);
  k_pool<<<NN,256>>>(batch);
  k_final<<<BB,256>>>(gW0,gb0,gW1,gb1,gW2,gb2,out);
}